// round 1
// baseline (speedup 1.0000x reference)
#include <cuda_runtime.h>
#include <math.h>

// Problem constants
#define BB 4
#define SS 1024
#define DD 1024
#define HH 16
#define HDD 64
#define EE 8
#define FF 4096
#define NTOK 4096      // B*S
#define NSLOT 8192     // NTOK * K(=2)
#define RMS_EPS 1e-6f
#define ATT_SCALE 0.125f   // 1/sqrt(64)

// ---------------- scratch (static device globals; no runtime allocation) ----
__device__ float g_xn[NTOK * DD];                 // normalized activations (reused)
__device__ float g_qh[NTOK * DD];
__device__ float g_kh[NTOK * DD];
__device__ float g_vh[NTOK * DD];
__device__ float g_att[NTOK * DD];
__device__ float g_h[NTOK * DD];                  // attention residual output
__device__ float g_hidden[(size_t)NSLOT * FF];    // MoE hidden (per slot)
__device__ float g_ypair[(size_t)NSLOT * DD];     // per-slot expert output
__device__ float g_gate[NSLOT];
__device__ int   g_expcnt[EE];
__device__ int   g_expslots[EE * NTOK];

// ---------------- RMSNorm ---------------------------------------------------
__global__ __launch_bounds__(256) void rmsnorm_kernel(
    const float* __restrict__ x, const float* __restrict__ w,
    float* __restrict__ out)
{
    int t = blockIdx.x;
    const float4* xr = (const float4*)(x + (size_t)t * DD);
    float4 v = xr[threadIdx.x];
    float ss = v.x * v.x + v.y * v.y + v.z * v.z + v.w * v.w;
    #pragma unroll
    for (int o = 16; o; o >>= 1) ss += __shfl_xor_sync(0xffffffffu, ss, o);
    __shared__ float sh[8];
    __shared__ float stot;
    int warp = threadIdx.x >> 5;
    if ((threadIdx.x & 31) == 0) sh[warp] = ss;
    __syncthreads();
    if (threadIdx.x == 0) {
        float s = 0.f;
        #pragma unroll
        for (int i = 0; i < 8; i++) s += sh[i];
        stot = rsqrtf(s / (float)DD + RMS_EPS);
    }
    __syncthreads();
    float sc = stot;
    float4 wv = ((const float4*)w)[threadIdx.x];
    float4 o;
    o.x = v.x * sc * wv.x; o.y = v.y * sc * wv.y;
    o.z = v.z * sc * wv.z; o.w = v.w * sc * wv.w;
    ((float4*)(out + (size_t)t * DD))[threadIdx.x] = o;
}

// ---------------- dense GEMM: C[M,N] = A[M,K] @ W[N,K]^T (+resid) -----------
// grid: (N/64, M/64), block 256
__global__ __launch_bounds__(256) void gemm_proj(
    const float* __restrict__ A, const float* __restrict__ W,
    const float* __restrict__ resid, float* __restrict__ C,
    int Kk, int Nn)
{
    __shared__ float As[16][68];
    __shared__ float Bs[16][68];
    const int tid = threadIdx.x;
    const int tx = tid & 15, ty = tid >> 4;
    const int m0 = blockIdx.y * 64, n0 = blockIdx.x * 64;
    const int lr = tid >> 2, lq = (tid & 3) * 4;
    float acc[4][4] = {};
    const float* Ap = A + (size_t)(m0 + lr) * Kk + lq;
    const float* Wp = W + (size_t)(n0 + lr) * Kk + lq;
    for (int k0 = 0; k0 < Kk; k0 += 16) {
        float4 av = *(const float4*)(Ap + k0);
        float4 bv = *(const float4*)(Wp + k0);
        As[lq + 0][lr] = av.x; As[lq + 1][lr] = av.y;
        As[lq + 2][lr] = av.z; As[lq + 3][lr] = av.w;
        Bs[lq + 0][lr] = bv.x; Bs[lq + 1][lr] = bv.y;
        Bs[lq + 2][lr] = bv.z; Bs[lq + 3][lr] = bv.w;
        __syncthreads();
        #pragma unroll
        for (int k = 0; k < 16; k++) {
            float a[4], b[4];
            #pragma unroll
            for (int i = 0; i < 4; i++) a[i] = As[k][ty * 4 + i];
            #pragma unroll
            for (int j = 0; j < 4; j++) b[j] = Bs[k][tx * 4 + j];
            #pragma unroll
            for (int i = 0; i < 4; i++)
                #pragma unroll
                for (int j = 0; j < 4; j++)
                    acc[i][j] = fmaf(a[i], b[j], acc[i][j]);
        }
        __syncthreads();
    }
    #pragma unroll
    for (int i = 0; i < 4; i++) {
        int m = m0 + ty * 4 + i;
        #pragma unroll
        for (int j = 0; j < 4; j++) {
            size_t idx = (size_t)m * Nn + n0 + tx * 4 + j;
            C[idx] = resid ? acc[i][j] + resid[idx] : acc[i][j];
        }
    }
}

// ---------------- expert GEMM (gathered rows via slot lists) ----------------
// mode 0: store raw A@w1^T into g_hidden[slot]
// mode 1: g_hidden[slot] = silu(prev) * (A@w3^T)
// mode 2: g_ypair[slot]  = A@w2^T          (A = g_hidden, row = slot)
// grid: (Nn/64, Mtiles, E), block 256
__global__ __launch_bounds__(256) void gemm_expert(
    const float* __restrict__ A, int lda, int rowIsToken,
    const float* __restrict__ Wbase, int Kk, int Nn, int mode)
{
    const int e = blockIdx.z;
    const int count = g_expcnt[e];
    const int m0 = blockIdx.y * 64;
    if (m0 >= count) return;
    __shared__ float As[16][68];
    __shared__ float Bs[16][68];
    __shared__ int srow[64];
    const int tid = threadIdx.x;
    if (tid < 64) {
        int r = m0 + tid;
        srow[tid] = (r < count) ? g_expslots[e * NTOK + r] : -1;
    }
    __syncthreads();
    const int tx = tid & 15, ty = tid >> 4;
    const int n0 = blockIdx.x * 64;
    const int lr = tid >> 2, lq = (tid & 3) * 4;
    const float* W = Wbase + (size_t)e * Nn * Kk;
    const int slot = srow[lr];
    const float* Ap = nullptr;
    if (slot >= 0) {
        int arow = rowIsToken ? (slot >> 1) : slot;
        Ap = A + (size_t)arow * lda + lq;
    }
    const float* Wp = W + (size_t)(n0 + lr) * Kk + lq;
    float acc[4][4] = {};
    for (int k0 = 0; k0 < Kk; k0 += 16) {
        float4 av = Ap ? *(const float4*)(Ap + k0) : make_float4(0.f, 0.f, 0.f, 0.f);
        float4 bv = *(const float4*)(Wp + k0);
        As[lq + 0][lr] = av.x; As[lq + 1][lr] = av.y;
        As[lq + 2][lr] = av.z; As[lq + 3][lr] = av.w;
        Bs[lq + 0][lr] = bv.x; Bs[lq + 1][lr] = bv.y;
        Bs[lq + 2][lr] = bv.z; Bs[lq + 3][lr] = bv.w;
        __syncthreads();
        #pragma unroll
        for (int k = 0; k < 16; k++) {
            float a[4], b[4];
            #pragma unroll
            for (int i = 0; i < 4; i++) a[i] = As[k][ty * 4 + i];
            #pragma unroll
            for (int j = 0; j < 4; j++) b[j] = Bs[k][tx * 4 + j];
            #pragma unroll
            for (int i = 0; i < 4; i++)
                #pragma unroll
                for (int j = 0; j < 4; j++)
                    acc[i][j] = fmaf(a[i], b[j], acc[i][j]);
        }
        __syncthreads();
    }
    #pragma unroll
    for (int i = 0; i < 4; i++) {
        int m = ty * 4 + i;
        int s = srow[m];
        if (s < 0) continue;
        #pragma unroll
        for (int j = 0; j < 4; j++) {
            int n = n0 + tx * 4 + j;
            if (mode == 0) {
                g_hidden[(size_t)s * FF + n] = acc[i][j];
            } else if (mode == 1) {
                size_t idx = (size_t)s * FF + n;
                float h1 = g_hidden[idx];
                g_hidden[idx] = (h1 / (1.f + expf(-h1))) * acc[i][j];
            } else {
                g_ypair[(size_t)s * DD + n] = acc[i][j];
            }
        }
    }
}

// ---------------- RoPE (q and k in place) -----------------------------------
__global__ void rope_kernel(float* __restrict__ qh, float* __restrict__ kh,
                            const float* __restrict__ cosb,
                            const float* __restrict__ sinb)
{
    int idx = blockIdx.x * blockDim.x + threadIdx.x;   // pair index
    int i = idx & 31;            // HD/2 = 32
    int th = idx >> 5;           // token*H + h
    int t = th >> 4;             // token
    int s = t & (SS - 1);
    float c = cosb[s * 32 + i], sn = sinb[s * 32 + i];
    size_t base = (size_t)th * HDD + i * 2;
    float xr = qh[base], xi = qh[base + 1];
    qh[base]     = xr * c - xi * sn;
    qh[base + 1] = xr * sn + xi * c;
    xr = kh[base]; xi = kh[base + 1];
    kh[base]     = xr * c - xi * sn;
    kh[base + 1] = xr * sn + xi * c;
}

// ---------------- Flash attention (fp32, 64x64 tiles) -----------------------
// grid (S/64, B*H), block 256, dynamic smem 4*64*65*4 bytes
#define ATT_STRIDE 65
__global__ __launch_bounds__(256) void attn_kernel(
    const float* __restrict__ Q, const float* __restrict__ Kt,
    const float* __restrict__ V, float* __restrict__ O,
    const int* __restrict__ causal_flag)
{
    extern __shared__ float sm[];
    float* Qs = sm;
    float* Ks = Qs + 64 * ATT_STRIDE;
    float* Vs = Ks + 64 * ATT_STRIDE;
    float* Ps = Vs + 64 * ATT_STRIDE;
    const int qt = blockIdx.x;
    const int bh = blockIdx.y;
    const int b = bh >> 4, h = bh & 15;
    const int tid = threadIdx.x;
    const int lr = tid >> 2, lq = (tid & 3) * 16;
    const int causal = *causal_flag;
    const size_t headoff = (size_t)h * HDD;
    const float* Qb = Q + (size_t)b * SS * DD + headoff;
    const float* Kb = Kt + (size_t)b * SS * DD + headoff;
    const float* Vb = V + (size_t)b * SS * DD + headoff;

    {   // load Q tile
        const float* src = Qb + (size_t)(qt * 64 + lr) * DD + lq;
        #pragma unroll
        for (int j4 = 0; j4 < 4; j4++) {
            float4 v = *(const float4*)(src + j4 * 4);
            Qs[lr * ATT_STRIDE + lq + j4 * 4 + 0] = v.x;
            Qs[lr * ATT_STRIDE + lq + j4 * 4 + 1] = v.y;
            Qs[lr * ATT_STRIDE + lq + j4 * 4 + 2] = v.z;
            Qs[lr * ATT_STRIDE + lq + j4 * 4 + 3] = v.w;
        }
    }

    const int r = tid >> 2, g = tid & 3;
    float m_run = -1e30f, l_run = 0.f;
    float Oacc[16];
    #pragma unroll
    for (int i = 0; i < 16; i++) Oacc[i] = 0.f;

    const int ktmax = causal ? qt : (SS / 64 - 1);
    for (int kt = 0; kt <= ktmax; kt++) {
        __syncthreads();   // protect Ks/Vs from previous iteration readers
        {
            const float* ks = Kb + (size_t)(kt * 64 + lr) * DD + lq;
            const float* vs = Vb + (size_t)(kt * 64 + lr) * DD + lq;
            #pragma unroll
            for (int j4 = 0; j4 < 4; j4++) {
                float4 kv = *(const float4*)(ks + j4 * 4);
                float4 vv = *(const float4*)(vs + j4 * 4);
                int o = lr * ATT_STRIDE + lq + j4 * 4;
                Ks[o + 0] = kv.x; Ks[o + 1] = kv.y; Ks[o + 2] = kv.z; Ks[o + 3] = kv.w;
                Vs[o + 0] = vv.x; Vs[o + 1] = vv.y; Vs[o + 2] = vv.z; Vs[o + 3] = vv.w;
            }
        }
        __syncthreads();

        float sv[16];
        const float* qr = &Qs[r * ATT_STRIDE];
        #pragma unroll
        for (int cj = 0; cj < 16; cj++) {
            const float* kr = &Ks[(g * 16 + cj) * ATT_STRIDE];
            float sacc = 0.f;
            #pragma unroll
            for (int d = 0; d < 64; d++) sacc = fmaf(qr[d], kr[d], sacc);
            sv[cj] = sacc * ATT_SCALE;
        }
        if (causal && kt == qt) {
            #pragma unroll
            for (int cj = 0; cj < 16; cj++) {
                int c = g * 16 + cj;
                if (c > r) sv[cj] = -1e30f;
            }
        }
        float mloc = sv[0];
        #pragma unroll
        for (int cj = 1; cj < 16; cj++) mloc = fmaxf(mloc, sv[cj]);
        mloc = fmaxf(mloc, __shfl_xor_sync(0xffffffffu, mloc, 1));
        mloc = fmaxf(mloc, __shfl_xor_sync(0xffffffffu, mloc, 2));
        float m_new = fmaxf(m_run, mloc);
        float alpha = expf(m_run - m_new);
        float psum = 0.f;
        #pragma unroll
        for (int cj = 0; cj < 16; cj++) {
            float p = expf(sv[cj] - m_new);
            Ps[r * ATT_STRIDE + g * 16 + cj] = p;
            psum += p;
        }
        psum += __shfl_xor_sync(0xffffffffu, psum, 1);
        psum += __shfl_xor_sync(0xffffffffu, psum, 2);
        l_run = l_run * alpha + psum;
        m_run = m_new;
        __syncwarp();   // Ps row written/read only within this warp's 4-lane groups

        #pragma unroll
        for (int i = 0; i < 16; i++) Oacc[i] *= alpha;
        const float* pr = &Ps[r * ATT_STRIDE];
        for (int c = 0; c < 64; c++) {
            float p = pr[c];
            const float* vr = &Vs[c * ATT_STRIDE + g * 16];
            #pragma unroll
            for (int i = 0; i < 16; i++) Oacc[i] = fmaf(p, vr[i], Oacc[i]);
        }
    }

    float inv = 1.f / l_run;
    float* dst = O + (size_t)(b * SS + qt * 64 + r) * DD + headoff + g * 16;
    #pragma unroll
    for (int i = 0; i < 16; i++) dst[i] = Oacc[i] * inv;
}

// ---------------- router + top-2 --------------------------------------------
__global__ void zero_counts_kernel()
{
    if (threadIdx.x < EE) g_expcnt[threadIdx.x] = 0;
}

__global__ __launch_bounds__(256) void router_kernel(
    const float* __restrict__ xn, const float* __restrict__ rw,
    const float* __restrict__ rb)
{
    int t = blockIdx.x;
    float4 xv = ((const float4*)(xn + (size_t)t * DD))[threadIdx.x];
    float lg[EE];
    #pragma unroll
    for (int e = 0; e < EE; e++) {
        float4 wv = ((const float4*)(rw + (size_t)e * DD))[threadIdx.x];
        lg[e] = xv.x * wv.x + xv.y * wv.y + xv.z * wv.z + xv.w * wv.w;
    }
    #pragma unroll
    for (int o = 16; o; o >>= 1)
        #pragma unroll
        for (int e = 0; e < EE; e++)
            lg[e] += __shfl_xor_sync(0xffffffffu, lg[e], o);
    __shared__ float sh[EE][8];
    int warp = threadIdx.x >> 5;
    if ((threadIdx.x & 31) == 0)
        #pragma unroll
        for (int e = 0; e < EE; e++) sh[e][warp] = lg[e];
    __syncthreads();
    if (threadIdx.x == 0) {
        float logits[EE];
        #pragma unroll
        for (int e = 0; e < EE; e++) {
            float s = rb[e];
            #pragma unroll
            for (int w = 0; w < 8; w++) s += sh[e][w];
            logits[e] = s;
        }
        int i0 = 0;
        #pragma unroll
        for (int e = 1; e < EE; e++) if (logits[e] > logits[i0]) i0 = e;
        int i1 = -1;
        #pragma unroll
        for (int e = 0; e < EE; e++)
            if (e != i0 && (i1 < 0 || logits[e] > logits[i1])) i1 = e;
        float ex = expf(logits[i1] - logits[i0]);
        float denom = 1.f + ex;
        float p0 = 1.f / denom, p1 = ex / denom;
        int s0 = atomicAdd(&g_expcnt[i0], 1);
        g_expslots[i0 * NTOK + s0] = 2 * t;
        g_gate[2 * t] = p0;
        int s1 = atomicAdd(&g_expcnt[i1], 1);
        g_expslots[i1 * NTOK + s1] = 2 * t + 1;
        g_gate[2 * t + 1] = p1;
    }
}

// ---------------- final combine ---------------------------------------------
__global__ __launch_bounds__(256) void combine_kernel(float* __restrict__ out)
{
    int idx = blockIdx.x * 256 + threadIdx.x;   // float4 index into [NTOK, D]
    int t = idx >> 8;                            // 256 float4 per token
    int col = idx & 255;
    float g0 = g_gate[2 * t], g1 = g_gate[2 * t + 1];
    float4 hv = ((const float4*)g_h)[idx];
    float4 y0 = ((const float4*)g_ypair)[(size_t)(2 * t) * 256 + col];
    float4 y1 = ((const float4*)g_ypair)[(size_t)(2 * t + 1) * 256 + col];
    float4 o;
    o.x = hv.x + g0 * y0.x + g1 * y1.x;
    o.y = hv.y + g0 * y0.y + g1 * y1.y;
    o.z = hv.z + g0 * y0.z + g1 * y1.z;
    o.w = hv.w + g0 * y0.w + g1 * y1.w;
    ((float4*)out)[idx] = o;
}

// ---------------- launch ----------------------------------------------------
extern "C" void kernel_launch(void* const* d_in, const int* in_sizes, int n_in,
                              void* d_out, int out_size)
{
    const float* q     = (const float*)d_in[0];
    // d_in[1] (k), d_in[2] (v) are unused by the reference (attention uses qn for all three)
    const float* fcos  = (const float*)d_in[3];
    const float* fsin  = (const float*)d_in[4];
    const float* att_w = (const float*)d_in[5];
    const float* ffn_w = (const float*)d_in[6];
    const float* wq    = (const float*)d_in[7];
    const float* wk    = (const float*)d_in[8];
    const float* wv    = (const float*)d_in[9];
    const float* wo    = (const float*)d_in[10];
    const float* rw    = (const float*)d_in[11];
    const float* rb    = (const float*)d_in[12];
    const float* w1    = (const float*)d_in[13];
    const float* w2    = (const float*)d_in[14];
    const float* w3    = (const float*)d_in[15];
    const int*   causal= (const int*)d_in[16];
    float* out = (float*)d_out;

    float *p_xn, *p_qh, *p_kh, *p_vh, *p_att, *p_h;
    cudaGetSymbolAddress((void**)&p_xn, g_xn);
    cudaGetSymbolAddress((void**)&p_qh, g_qh);
    cudaGetSymbolAddress((void**)&p_kh, g_kh);
    cudaGetSymbolAddress((void**)&p_vh, g_vh);
    cudaGetSymbolAddress((void**)&p_att, g_att);
    cudaGetSymbolAddress((void**)&p_h, g_h);
    float* p_hidden;
    cudaGetSymbolAddress((void**)&p_hidden, g_hidden);

    const size_t attn_smem = 4 * 64 * ATT_STRIDE * sizeof(float);
    cudaFuncSetAttribute(attn_kernel,
                         cudaFuncAttributeMaxDynamicSharedMemorySize,
                         (int)attn_smem);

    // 1. qn = rmsnorm(q) * att_norm_w
    rmsnorm_kernel<<<NTOK, 256>>>(q, att_w, p_xn);

    // 2. QKV projections
    dim3 gproj(DD / 64, NTOK / 64);
    gemm_proj<<<gproj, 256>>>(p_xn, wq, nullptr, p_qh, DD, DD);
    gemm_proj<<<gproj, 256>>>(p_xn, wk, nullptr, p_kh, DD, DD);
    gemm_proj<<<gproj, 256>>>(p_xn, wv, nullptr, p_vh, DD, DD);

    // 3. RoPE on q,k
    rope_kernel<<<(NTOK * HH * (HDD / 2)) / 256, 256>>>(p_qh, p_kh, fcos, fsin);

    // 4. flash attention
    attn_kernel<<<dim3(SS / 64, BB * HH), 256, attn_smem>>>(p_qh, p_kh, p_vh, p_att, causal);

    // 5. output projection + residual: h = q + att @ wo^T
    gemm_proj<<<gproj, 256>>>(p_att, wo, q, p_h, DD, DD);

    // 6. hn = rmsnorm(h) * ffn_norm_w
    rmsnorm_kernel<<<NTOK, 256>>>(p_h, ffn_w, p_xn);

    // 7. routing
    zero_counts_kernel<<<1, 32>>>();
    router_kernel<<<NTOK, 256>>>(p_xn, rw, rb);

    // 8. MoE expert GEMMs (sparse, per-expert slot lists)
    dim3 g1(FF / 64, NTOK / 64, EE);
    gemm_expert<<<g1, 256>>>(p_xn, DD, 1, w1, DD, FF, 0);   // raw h1
    gemm_expert<<<g1, 256>>>(p_xn, DD, 1, w3, DD, FF, 1);   // hidden = silu(h1)*h3
    dim3 g2(DD / 64, NTOK / 64, EE);
    gemm_expert<<<g2, 256>>>(p_hidden, FF, 0, w2, FF, DD, 2);  // ypair

    // 9. out = h + gates * expert outputs
    combine_kernel<<<NTOK, 256>>>(out);
}

// round 3
// speedup vs baseline: 2.0994x; 2.0994x over previous
#include <cuda_runtime.h>
#include <math.h>
#include <stdint.h>

// Problem constants
#define BB 4
#define SS 1024
#define DD 1024
#define HH 16
#define HDD 64
#define EE 8
#define FF 4096
#define NTOK 4096      // B*S
#define NSLOT 8192     // NTOK * K(=2)
#define RMS_EPS 1e-6f
#define ATT_SCALE 0.125f   // 1/sqrt(64)

// ---------------- scratch (static device globals; no runtime allocation) ----
__device__ float g_xn[NTOK * DD];
__device__ float g_qh[NTOK * DD];
__device__ float g_kh[NTOK * DD];
__device__ float g_vh[NTOK * DD];
__device__ float g_att[NTOK * DD];
__device__ float g_h[NTOK * DD];
__device__ float g_hidden[(size_t)NSLOT * FF];
__device__ float g_ypair[(size_t)NSLOT * DD];
__device__ float g_gate[NSLOT];
__device__ int   g_expcnt[EE];
__device__ int   g_expslots[EE * NTOK];

// ---------------- helpers ---------------------------------------------------
__device__ __forceinline__ uint32_t f2tf32(float f) {
    uint32_t u;
    asm("cvt.rna.tf32.f32 %0, %1;" : "=r"(u) : "f"(f));
    return u;
}

__device__ __forceinline__ void mma_tf32(float* c, const uint32_t* a, const uint32_t* b) {
    asm volatile(
        "mma.sync.aligned.m16n8k8.row.col.f32.tf32.tf32.f32 "
        "{%0,%1,%2,%3}, {%4,%5,%6,%7}, {%8,%9}, {%0,%1,%2,%3};\n"
        : "+f"(c[0]), "+f"(c[1]), "+f"(c[2]), "+f"(c[3])
        : "r"(a[0]), "r"(a[1]), "r"(a[2]), "r"(a[3]), "r"(b[0]), "r"(b[1]));
}

// Smem tile: [128 rows][36 floats] (stride 36 => 16B-aligned rows, and compute
// loads hit bank (4g+t)%32 which is conflict-free across the warp).
#define TSTR 36

// ---------------- RMSNorm ---------------------------------------------------
__global__ __launch_bounds__(256) void rmsnorm_kernel(
    const float* __restrict__ x, const float* __restrict__ w,
    float* __restrict__ out)
{
    int t = blockIdx.x;
    const float4* xr = (const float4*)(x + (size_t)t * DD);
    float4 v = xr[threadIdx.x];
    float ss = v.x * v.x + v.y * v.y + v.z * v.z + v.w * v.w;
    #pragma unroll
    for (int o = 16; o; o >>= 1) ss += __shfl_xor_sync(0xffffffffu, ss, o);
    __shared__ float sh[8];
    __shared__ float stot;
    int warp = threadIdx.x >> 5;
    if ((threadIdx.x & 31) == 0) sh[warp] = ss;
    __syncthreads();
    if (threadIdx.x == 0) {
        float s = 0.f;
        #pragma unroll
        for (int i = 0; i < 8; i++) s += sh[i];
        stot = rsqrtf(s / (float)DD + RMS_EPS);
    }
    __syncthreads();
    float sc = stot;
    float4 wv = ((const float4*)w)[threadIdx.x];
    float4 o;
    o.x = v.x * sc * wv.x; o.y = v.y * sc * wv.y;
    o.z = v.z * sc * wv.z; o.w = v.w * sc * wv.w;
    ((float4*)(out + (size_t)t * DD))[threadIdx.x] = o;
}

// ---------------- dense tf32 tensor-core GEMM -------------------------------
// C[M,N] = A[M,K] @ W[N,K]^T (+resid). grid (N/128, M/128), block 256.
__global__ __launch_bounds__(256) void gemm_mma_proj(
    const float* __restrict__ A, const float* __restrict__ W,
    const float* __restrict__ resid, float* __restrict__ C,
    int Kk, int Nn)
{
    __shared__ uint32_t As[128 * TSTR];
    __shared__ uint32_t Bs[128 * TSTR];
    const int tid = threadIdx.x;
    const int lane = tid & 31, warp = tid >> 5;
    const int warpM = warp >> 2, warpN = warp & 3;   // 2 x 4 warp grid
    const int g = lane >> 2, t = lane & 3;
    const int m0 = blockIdx.y * 128, n0 = blockIdx.x * 128;
    float acc[4][4][4] = {};

    const int lrow = tid >> 3;              // base row for loads (stride 32)
    const int lkf = (tid & 7) * 4;          // k offset (float4)

    for (int kt = 0; kt < Kk; kt += 32) {
        #pragma unroll
        for (int i = 0; i < 4; i++) {
            int row = lrow + i * 32;
            float4 va = *(const float4*)(A + (size_t)(m0 + row) * Kk + kt + lkf);
            uint32_t* dst = &As[row * TSTR + lkf];
            dst[0] = f2tf32(va.x); dst[1] = f2tf32(va.y);
            dst[2] = f2tf32(va.z); dst[3] = f2tf32(va.w);
            float4 vb = *(const float4*)(W + (size_t)(n0 + row) * Kk + kt + lkf);
            uint32_t* dsb = &Bs[row * TSTR + lkf];
            dsb[0] = f2tf32(vb.x); dsb[1] = f2tf32(vb.y);
            dsb[2] = f2tf32(vb.z); dsb[3] = f2tf32(vb.w);
        }
        __syncthreads();
        #pragma unroll
        for (int k8 = 0; k8 < 4; k8++) {
            int kb = k8 * 8;
            uint32_t bf[4][2];
            #pragma unroll
            for (int ni = 0; ni < 4; ni++) {
                int n = warpN * 32 + ni * 8 + g;
                bf[ni][0] = Bs[n * TSTR + kb + t];
                bf[ni][1] = Bs[n * TSTR + kb + t + 4];
            }
            #pragma unroll
            for (int mi = 0; mi < 4; mi++) {
                int m = warpM * 64 + mi * 16 + g;
                uint32_t af[4];
                af[0] = As[m * TSTR + kb + t];
                af[1] = As[(m + 8) * TSTR + kb + t];
                af[2] = As[m * TSTR + kb + t + 4];
                af[3] = As[(m + 8) * TSTR + kb + t + 4];
                #pragma unroll
                for (int ni = 0; ni < 4; ni++)
                    mma_tf32(acc[mi][ni], af, bf[ni]);
            }
        }
        __syncthreads();
    }

    #pragma unroll
    for (int mi = 0; mi < 4; mi++) {
        int r0 = m0 + warpM * 64 + mi * 16 + g;
        #pragma unroll
        for (int ni = 0; ni < 4; ni++) {
            int c = n0 + warpN * 32 + ni * 8 + 2 * t;
            size_t i0 = (size_t)r0 * Nn + c;
            size_t i1 = i0 + (size_t)8 * Nn;
            float2 v0 = make_float2(acc[mi][ni][0], acc[mi][ni][1]);
            float2 v1 = make_float2(acc[mi][ni][2], acc[mi][ni][3]);
            if (resid) {
                float2 r = *(const float2*)(resid + i0); v0.x += r.x; v0.y += r.y;
                r = *(const float2*)(resid + i1); v1.x += r.x; v1.y += r.y;
            }
            *(float2*)(C + i0) = v0;
            *(float2*)(C + i1) = v1;
        }
    }
}

// ---------------- expert tf32 GEMM (gathered rows) --------------------------
// mode 0: g_hidden[slot] = A@w1^T
// mode 1: g_hidden[slot] = silu(g_hidden[slot]) * (A@w3^T)
// mode 2: g_ypair[slot]  = A@w2^T
// grid (Nn/128, NTOK/128, E), block 256.
__global__ __launch_bounds__(256) void gemm_mma_expert(
    const float* __restrict__ A, int lda, int rowIsToken,
    const float* __restrict__ Wbase, int Kk, int Nn, int mode)
{
    const int e = blockIdx.z;
    const int count = g_expcnt[e];
    const int m0 = blockIdx.y * 128;
    if (m0 >= count) return;

    __shared__ uint32_t As[128 * TSTR];
    __shared__ uint32_t Bs[128 * TSTR];
    __shared__ int srow[128];

    const int tid = threadIdx.x;
    if (tid < 128) {
        int r = m0 + tid;
        srow[tid] = (r < count) ? g_expslots[e * NTOK + r] : -1;
    }
    __syncthreads();

    const int lane = tid & 31, warp = tid >> 5;
    const int warpM = warp >> 2, warpN = warp & 3;
    const int g = lane >> 2, t = lane & 3;
    const int n0 = blockIdx.x * 128;
    const float* W = Wbase + (size_t)e * Nn * Kk;
    float acc[4][4][4] = {};

    const int lrow = tid >> 3;
    const int lkf = (tid & 7) * 4;

    // precompute gathered row pointers for the 4 loader rows
    const float* arp[4];
    #pragma unroll
    for (int i = 0; i < 4; i++) {
        int s = srow[lrow + i * 32];
        if (s >= 0) {
            int arow = rowIsToken ? (s >> 1) : s;
            arp[i] = A + (size_t)arow * lda + lkf;
        } else {
            arp[i] = nullptr;
        }
    }

    for (int kt = 0; kt < Kk; kt += 32) {
        #pragma unroll
        for (int i = 0; i < 4; i++) {
            int row = lrow + i * 32;
            float4 va = arp[i] ? *(const float4*)(arp[i] + kt)
                               : make_float4(0.f, 0.f, 0.f, 0.f);
            uint32_t* dst = &As[row * TSTR + lkf];
            dst[0] = f2tf32(va.x); dst[1] = f2tf32(va.y);
            dst[2] = f2tf32(va.z); dst[3] = f2tf32(va.w);
            float4 vb = *(const float4*)(W + (size_t)(n0 + row) * Kk + kt + lkf);
            uint32_t* dsb = &Bs[row * TSTR + lkf];
            dsb[0] = f2tf32(vb.x); dsb[1] = f2tf32(vb.y);
            dsb[2] = f2tf32(vb.z); dsb[3] = f2tf32(vb.w);
        }
        __syncthreads();
        #pragma unroll
        for (int k8 = 0; k8 < 4; k8++) {
            int kb = k8 * 8;
            uint32_t bf[4][2];
            #pragma unroll
            for (int ni = 0; ni < 4; ni++) {
                int n = warpN * 32 + ni * 8 + g;
                bf[ni][0] = Bs[n * TSTR + kb + t];
                bf[ni][1] = Bs[n * TSTR + kb + t + 4];
            }
            #pragma unroll
            for (int mi = 0; mi < 4; mi++) {
                int m = warpM * 64 + mi * 16 + g;
                uint32_t af[4];
                af[0] = As[m * TSTR + kb + t];
                af[1] = As[(m + 8) * TSTR + kb + t];
                af[2] = As[m * TSTR + kb + t + 4];
                af[3] = As[(m + 8) * TSTR + kb + t + 4];
                #pragma unroll
                for (int ni = 0; ni < 4; ni++)
                    mma_tf32(acc[mi][ni], af, bf[ni]);
            }
        }
        __syncthreads();
    }

    #pragma unroll
    for (int mi = 0; mi < 4; mi++) {
        int mloc0 = warpM * 64 + mi * 16 + g;
        #pragma unroll
        for (int half = 0; half < 2; half++) {
            int mloc = mloc0 + half * 8;
            int s = srow[mloc];
            if (s < 0) continue;
            #pragma unroll
            for (int ni = 0; ni < 4; ni++) {
                int c = n0 + warpN * 32 + ni * 8 + 2 * t;
                float2 v = make_float2(acc[mi][ni][half * 2],
                                       acc[mi][ni][half * 2 + 1]);
                if (mode == 0) {
                    *(float2*)(&g_hidden[(size_t)s * FF + c]) = v;
                } else if (mode == 1) {
                    float2 h1 = *(const float2*)(&g_hidden[(size_t)s * FF + c]);
                    float2 o;
                    o.x = (h1.x / (1.f + expf(-h1.x))) * v.x;
                    o.y = (h1.y / (1.f + expf(-h1.y))) * v.y;
                    *(float2*)(&g_hidden[(size_t)s * FF + c]) = o;
                } else {
                    *(float2*)(&g_ypair[(size_t)s * DD + c]) = v;
                }
            }
        }
    }
}

// ---------------- RoPE (q and k in place) -----------------------------------
__global__ void rope_kernel(float* __restrict__ qh, float* __restrict__ kh,
                            const float* __restrict__ cosb,
                            const float* __restrict__ sinb)
{
    int idx = blockIdx.x * blockDim.x + threadIdx.x;
    int i = idx & 31;
    int th = idx >> 5;
    int t = th >> 4;
    int s = t & (SS - 1);
    float c = cosb[s * 32 + i], sn = sinb[s * 32 + i];
    size_t base = (size_t)th * HDD + i * 2;
    float xr = qh[base], xi = qh[base + 1];
    qh[base]     = xr * c - xi * sn;
    qh[base + 1] = xr * sn + xi * c;
    xr = kh[base]; xi = kh[base + 1];
    kh[base]     = xr * c - xi * sn;
    kh[base + 1] = xr * sn + xi * c;
}

// ---------------- Flash attention (fp32, 64x64 tiles) -----------------------
#define ATT_STRIDE 65
__global__ __launch_bounds__(256) void attn_kernel(
    const float* __restrict__ Q, const float* __restrict__ Kt,
    const float* __restrict__ V, float* __restrict__ O,
    const int* __restrict__ causal_flag)
{
    extern __shared__ float sm[];
    float* Qs = sm;
    float* Ks = Qs + 64 * ATT_STRIDE;
    float* Vs = Ks + 64 * ATT_STRIDE;
    float* Ps = Vs + 64 * ATT_STRIDE;
    const int qt = blockIdx.x;
    const int bh = blockIdx.y;
    const int b = bh >> 4, h = bh & 15;
    const int tid = threadIdx.x;
    const int lr = tid >> 2, lq = (tid & 3) * 16;
    const int causal = *causal_flag;
    const size_t headoff = (size_t)h * HDD;
    const float* Qb = Q + (size_t)b * SS * DD + headoff;
    const float* Kb = Kt + (size_t)b * SS * DD + headoff;
    const float* Vb = V + (size_t)b * SS * DD + headoff;

    {
        const float* src = Qb + (size_t)(qt * 64 + lr) * DD + lq;
        #pragma unroll
        for (int j4 = 0; j4 < 4; j4++) {
            float4 v = *(const float4*)(src + j4 * 4);
            Qs[lr * ATT_STRIDE + lq + j4 * 4 + 0] = v.x;
            Qs[lr * ATT_STRIDE + lq + j4 * 4 + 1] = v.y;
            Qs[lr * ATT_STRIDE + lq + j4 * 4 + 2] = v.z;
            Qs[lr * ATT_STRIDE + lq + j4 * 4 + 3] = v.w;
        }
    }

    const int r = tid >> 2, g = tid & 3;
    float m_run = -1e30f, l_run = 0.f;
    float Oacc[16];
    #pragma unroll
    for (int i = 0; i < 16; i++) Oacc[i] = 0.f;

    const int ktmax = causal ? qt : (SS / 64 - 1);
    for (int kt = 0; kt <= ktmax; kt++) {
        __syncthreads();
        {
            const float* ks = Kb + (size_t)(kt * 64 + lr) * DD + lq;
            const float* vs = Vb + (size_t)(kt * 64 + lr) * DD + lq;
            #pragma unroll
            for (int j4 = 0; j4 < 4; j4++) {
                float4 kv = *(const float4*)(ks + j4 * 4);
                float4 vv = *(const float4*)(vs + j4 * 4);
                int o = lr * ATT_STRIDE + lq + j4 * 4;
                Ks[o + 0] = kv.x; Ks[o + 1] = kv.y; Ks[o + 2] = kv.z; Ks[o + 3] = kv.w;
                Vs[o + 0] = vv.x; Vs[o + 1] = vv.y; Vs[o + 2] = vv.z; Vs[o + 3] = vv.w;
            }
        }
        __syncthreads();

        float sv[16];
        const float* qr = &Qs[r * ATT_STRIDE];
        #pragma unroll
        for (int cj = 0; cj < 16; cj++) {
            const float* kr = &Ks[(g * 16 + cj) * ATT_STRIDE];
            float sacc = 0.f;
            #pragma unroll
            for (int d = 0; d < 64; d++) sacc = fmaf(qr[d], kr[d], sacc);
            sv[cj] = sacc * ATT_SCALE;
        }
        if (causal && kt == qt) {
            #pragma unroll
            for (int cj = 0; cj < 16; cj++) {
                int c = g * 16 + cj;
                if (c > r) sv[cj] = -1e30f;
            }
        }
        float mloc = sv[0];
        #pragma unroll
        for (int cj = 1; cj < 16; cj++) mloc = fmaxf(mloc, sv[cj]);
        mloc = fmaxf(mloc, __shfl_xor_sync(0xffffffffu, mloc, 1));
        mloc = fmaxf(mloc, __shfl_xor_sync(0xffffffffu, mloc, 2));
        float m_new = fmaxf(m_run, mloc);
        float alpha = expf(m_run - m_new);
        float psum = 0.f;
        #pragma unroll
        for (int cj = 0; cj < 16; cj++) {
            float p = expf(sv[cj] - m_new);
            Ps[r * ATT_STRIDE + g * 16 + cj] = p;
            psum += p;
        }
        psum += __shfl_xor_sync(0xffffffffu, psum, 1);
        psum += __shfl_xor_sync(0xffffffffu, psum, 2);
        l_run = l_run * alpha + psum;
        m_run = m_new;
        __syncwarp();

        #pragma unroll
        for (int i = 0; i < 16; i++) Oacc[i] *= alpha;
        const float* pr = &Ps[r * ATT_STRIDE];
        for (int c = 0; c < 64; c++) {
            float p = pr[c];
            const float* vr = &Vs[c * ATT_STRIDE + g * 16];
            #pragma unroll
            for (int i = 0; i < 16; i++) Oacc[i] = fmaf(p, vr[i], Oacc[i]);
        }
    }

    float inv = 1.f / l_run;
    float* dst = O + (size_t)(b * SS + qt * 64 + r) * DD + headoff + g * 16;
    #pragma unroll
    for (int i = 0; i < 16; i++) dst[i] = Oacc[i] * inv;
}

// ---------------- router + top-2 --------------------------------------------
__global__ void zero_counts_kernel()
{
    if (threadIdx.x < EE) g_expcnt[threadIdx.x] = 0;
}

__global__ __launch_bounds__(256) void router_kernel(
    const float* __restrict__ xn, const float* __restrict__ rw,
    const float* __restrict__ rb)
{
    int t = blockIdx.x;
    float4 xv = ((const float4*)(xn + (size_t)t * DD))[threadIdx.x];
    float lg[EE];
    #pragma unroll
    for (int e = 0; e < EE; e++) {
        float4 wv = ((const float4*)(rw + (size_t)e * DD))[threadIdx.x];
        lg[e] = xv.x * wv.x + xv.y * wv.y + xv.z * wv.z + xv.w * wv.w;
    }
    #pragma unroll
    for (int o = 16; o; o >>= 1)
        #pragma unroll
        for (int e = 0; e < EE; e++)
            lg[e] += __shfl_xor_sync(0xffffffffu, lg[e], o);
    __shared__ float sh[EE][8];
    int warp = threadIdx.x >> 5;
    if ((threadIdx.x & 31) == 0)
        #pragma unroll
        for (int e = 0; e < EE; e++) sh[e][warp] = lg[e];
    __syncthreads();
    if (threadIdx.x == 0) {
        float logits[EE];
        #pragma unroll
        for (int e = 0; e < EE; e++) {
            float s = rb[e];
            #pragma unroll
            for (int w = 0; w < 8; w++) s += sh[e][w];
            logits[e] = s;
        }
        int i0 = 0;
        #pragma unroll
        for (int e = 1; e < EE; e++) if (logits[e] > logits[i0]) i0 = e;
        int i1 = -1;
        #pragma unroll
        for (int e = 0; e < EE; e++)
            if (e != i0 && (i1 < 0 || logits[e] > logits[i1])) i1 = e;
        float ex = expf(logits[i1] - logits[i0]);
        float denom = 1.f + ex;
        float p0 = 1.f / denom, p1 = ex / denom;
        int s0 = atomicAdd(&g_expcnt[i0], 1);
        g_expslots[i0 * NTOK + s0] = 2 * t;
        g_gate[2 * t] = p0;
        int s1 = atomicAdd(&g_expcnt[i1], 1);
        g_expslots[i1 * NTOK + s1] = 2 * t + 1;
        g_gate[2 * t + 1] = p1;
    }
}

// ---------------- final combine ---------------------------------------------
__global__ __launch_bounds__(256) void combine_kernel(float* __restrict__ out)
{
    int idx = blockIdx.x * 256 + threadIdx.x;
    int t = idx >> 8;
    int col = idx & 255;
    float g0 = g_gate[2 * t], g1 = g_gate[2 * t + 1];
    float4 hv = ((const float4*)g_h)[idx];
    float4 y0 = ((const float4*)g_ypair)[(size_t)(2 * t) * 256 + col];
    float4 y1 = ((const float4*)g_ypair)[(size_t)(2 * t + 1) * 256 + col];
    float4 o;
    o.x = hv.x + g0 * y0.x + g1 * y1.x;
    o.y = hv.y + g0 * y0.y + g1 * y1.y;
    o.z = hv.z + g0 * y0.z + g1 * y1.z;
    o.w = hv.w + g0 * y0.w + g1 * y1.w;
    ((float4*)out)[idx] = o;
}

// ---------------- launch ----------------------------------------------------
extern "C" void kernel_launch(void* const* d_in, const int* in_sizes, int n_in,
                              void* d_out, int out_size)
{
    const float* q     = (const float*)d_in[0];
    const float* fcos  = (const float*)d_in[3];
    const float* fsin  = (const float*)d_in[4];
    const float* att_w = (const float*)d_in[5];
    const float* ffn_w = (const float*)d_in[6];
    const float* wq    = (const float*)d_in[7];
    const float* wk    = (const float*)d_in[8];
    const float* wv    = (const float*)d_in[9];
    const float* wo    = (const float*)d_in[10];
    const float* rw    = (const float*)d_in[11];
    const float* rb    = (const float*)d_in[12];
    const float* w1    = (const float*)d_in[13];
    const float* w2    = (const float*)d_in[14];
    const float* w3    = (const float*)d_in[15];
    const int*   causal= (const int*)d_in[16];
    float* out = (float*)d_out;

    float *p_xn, *p_qh, *p_kh, *p_vh, *p_att, *p_h, *p_hidden;
    cudaGetSymbolAddress((void**)&p_xn, g_xn);
    cudaGetSymbolAddress((void**)&p_qh, g_qh);
    cudaGetSymbolAddress((void**)&p_kh, g_kh);
    cudaGetSymbolAddress((void**)&p_vh, g_vh);
    cudaGetSymbolAddress((void**)&p_att, g_att);
    cudaGetSymbolAddress((void**)&p_h, g_h);
    cudaGetSymbolAddress((void**)&p_hidden, g_hidden);

    const size_t attn_smem = 4 * 64 * ATT_STRIDE * sizeof(float);
    cudaFuncSetAttribute(attn_kernel,
                         cudaFuncAttributeMaxDynamicSharedMemorySize,
                         (int)attn_smem);

    // 1. qn = rmsnorm(q) * att_norm_w
    rmsnorm_kernel<<<NTOK, 256>>>(q, att_w, p_xn);

    // 2. QKV projections (tf32 tensor cores)
    dim3 gproj(DD / 128, NTOK / 128);
    gemm_mma_proj<<<gproj, 256>>>(p_xn, wq, nullptr, p_qh, DD, DD);
    gemm_mma_proj<<<gproj, 256>>>(p_xn, wk, nullptr, p_kh, DD, DD);
    gemm_mma_proj<<<gproj, 256>>>(p_xn, wv, nullptr, p_vh, DD, DD);

    // 3. RoPE
    rope_kernel<<<(NTOK * HH * (HDD / 2)) / 256, 256>>>(p_qh, p_kh, fcos, fsin);

    // 4. flash attention
    attn_kernel<<<dim3(SS / 64, BB * HH), 256, attn_smem>>>(p_qh, p_kh, p_vh, p_att, causal);

    // 5. h = q + att @ wo^T
    gemm_mma_proj<<<gproj, 256>>>(p_att, wo, q, p_h, DD, DD);

    // 6. hn = rmsnorm(h)
    rmsnorm_kernel<<<NTOK, 256>>>(p_h, ffn_w, p_xn);

    // 7. routing
    zero_counts_kernel<<<1, 32>>>();
    router_kernel<<<NTOK, 256>>>(p_xn, rw, rb);

    // 8. MoE expert GEMMs (tf32 tensor cores, sparse slot lists)
    dim3 g1(FF / 128, NTOK / 128, EE);
    gemm_mma_expert<<<g1, 256>>>(p_xn, DD, 1, w1, DD, FF, 0);
    gemm_mma_expert<<<g1, 256>>>(p_xn, DD, 1, w3, DD, FF, 1);
    dim3 g2(DD / 128, NTOK / 128, EE);
    gemm_mma_expert<<<g2, 256>>>(p_hidden, FF, 0, w2, FF, DD, 2);

    // 9. combine
    combine_kernel<<<NTOK, 256>>>(out);
}

// round 5
// speedup vs baseline: 2.4211x; 1.1533x over previous
#include <cuda_runtime.h>
#include <math.h>
#include <stdint.h>

// Problem constants
#define BB 4
#define SS 1024
#define DD 1024
#define HH 16
#define HDD 64
#define EE 8
#define FF 4096
#define NTOK 4096      // B*S
#define NSLOT 8192     // NTOK * K(=2)
#define RMS_EPS 1e-6f
#define ATT_SCALE 0.125f   // 1/sqrt(64)

// ---------------- scratch (static device globals; no runtime allocation) ----
__device__ float g_xn[NTOK * DD];
__device__ float g_qh[NTOK * DD];
__device__ float g_kh[NTOK * DD];
__device__ float g_vh[NTOK * DD];
__device__ float g_att[NTOK * DD];
__device__ float g_h[NTOK * DD];
__device__ float g_hidden[(size_t)NSLOT * FF];
__device__ float g_ypair[(size_t)NSLOT * DD];
__device__ float g_gate[NSLOT];
__device__ int   g_expcnt[EE];
__device__ int   g_expslots[EE * NTOK];

// ---------------- helpers ---------------------------------------------------
// fp32 register bits fed directly to tf32 mma: HW truncates trailing mantissa.
__device__ __forceinline__ void mma_tf32(float* c, const uint32_t* a, const uint32_t* b) {
    asm volatile(
        "mma.sync.aligned.m16n8k8.row.col.f32.tf32.tf32.f32 "
        "{%0,%1,%2,%3}, {%4,%5,%6,%7}, {%8,%9}, {%0,%1,%2,%3};\n"
        : "+f"(c[0]), "+f"(c[1]), "+f"(c[2]), "+f"(c[3])
        : "r"(a[0]), "r"(a[1]), "r"(a[2]), "r"(a[3]), "r"(b[0]), "r"(b[1]));
}

__device__ __forceinline__ void cp16(uint32_t dst, const void* src) {
    asm volatile("cp.async.cg.shared.global [%0], [%1], 16;\n"
                 :: "r"(dst), "l"(src));
}
// zero-fill variant: copies 16 bytes when ok!=0, else writes zeros (no gmem read)
__device__ __forceinline__ void cp16z(uint32_t dst, const void* src, int ok) {
    asm volatile("cp.async.cg.shared.global [%0], [%1], 16, %2;\n"
                 :: "r"(dst), "l"(src), "r"(ok ? 16 : 0));
}
__device__ __forceinline__ void cp_commit() {
    asm volatile("cp.async.commit_group;\n" ::: "memory");
}
template <int N>
__device__ __forceinline__ void cp_wait() {
    asm volatile("cp.async.wait_group %0;\n" :: "n"(N) : "memory");
}

// Smem tile: [128 rows][36 floats] (16B-aligned rows; compute LDS hits bank
// (4g+t)%32 -> conflict-free). Double-buffered A and B in dynamic smem.
#define TSTR 36
#define TILEW (128 * TSTR)                    // uint32 per tile
#define GEMM_SMEM (4 * TILEW * 4)             // bytes: 2 bufs x (A+B)

// ---------------- RMSNorm ---------------------------------------------------
__global__ __launch_bounds__(256) void rmsnorm_kernel(
    const float* __restrict__ x, const float* __restrict__ w,
    float* __restrict__ out)
{
    int t = blockIdx.x;
    const float4* xr = (const float4*)(x + (size_t)t * DD);
    float4 v = xr[threadIdx.x];
    float ss = v.x * v.x + v.y * v.y + v.z * v.z + v.w * v.w;
    #pragma unroll
    for (int o = 16; o; o >>= 1) ss += __shfl_xor_sync(0xffffffffu, ss, o);
    __shared__ float sh[8];
    __shared__ float stot;
    int warp = threadIdx.x >> 5;
    if ((threadIdx.x & 31) == 0) sh[warp] = ss;
    __syncthreads();
    if (threadIdx.x == 0) {
        float s = 0.f;
        #pragma unroll
        for (int i = 0; i < 8; i++) s += sh[i];
        stot = rsqrtf(s / (float)DD + RMS_EPS);
    }
    __syncthreads();
    float sc = stot;
    float4 wv = ((const float4*)w)[threadIdx.x];
    float4 o;
    o.x = v.x * sc * wv.x; o.y = v.y * sc * wv.y;
    o.z = v.z * sc * wv.z; o.w = v.w * sc * wv.w;
    ((float4*)(out + (size_t)t * DD))[threadIdx.x] = o;
}

// ---------------- dense tf32 tensor-core GEMM (cp.async pipelined) ----------
// C[M,N] = A[M,K] @ W[N,K]^T (+resid). grid (N/128, M/128), block 256.
__global__ __launch_bounds__(256) void gemm_mma_proj(
    const float* __restrict__ A, const float* __restrict__ W,
    const float* __restrict__ resid, float* __restrict__ C,
    int Kk, int Nn)
{
    extern __shared__ uint32_t smbuf[];
    uint32_t* As = smbuf;                  // [2][TILEW]
    uint32_t* Bs = smbuf + 2 * TILEW;      // [2][TILEW]
    const uint32_t smA = (uint32_t)__cvta_generic_to_shared(As);
    const uint32_t smB = (uint32_t)__cvta_generic_to_shared(Bs);

    const int tid = threadIdx.x;
    const int lane = tid & 31, warp = tid >> 5;
    const int warpM = warp >> 2, warpN = warp & 3;   // 2 x 4 warp grid
    const int g = lane >> 2, t = lane & 3;
    const int m0 = blockIdx.y * 128, n0 = blockIdx.x * 128;
    float acc[4][4][4] = {};

    const int lrow = tid >> 3;              // base row for loads (stride 32)
    const int lkf = (tid & 7) * 4;          // k offset (floats)

    const float* Ap = A + (size_t)(m0 + lrow) * Kk + lkf;
    const float* Wp = W + (size_t)(n0 + lrow) * Kk + lkf;
    const uint32_t dA0 = smA + (lrow * TSTR + lkf) * 4;
    const uint32_t dB0 = smB + (lrow * TSTR + lkf) * 4;

    const int nt = Kk >> 5;
    // prologue: tile 0 -> buf 0
    #pragma unroll
    for (int i = 0; i < 4; i++) {
        cp16(dA0 + i * 32 * TSTR * 4, Ap + (size_t)i * 32 * Kk);
        cp16(dB0 + i * 32 * TSTR * 4, Wp + (size_t)i * 32 * Kk);
    }
    cp_commit();

    for (int kt = 0; kt < nt; kt++) {
        const int buf = kt & 1;
        if (kt + 1 < nt) {
            const int koff = (kt + 1) * 32;
            const uint32_t bo = (buf ^ 1) * TILEW * 4;
            #pragma unroll
            for (int i = 0; i < 4; i++) {
                cp16(dA0 + bo + i * 32 * TSTR * 4, Ap + (size_t)i * 32 * Kk + koff);
                cp16(dB0 + bo + i * 32 * TSTR * 4, Wp + (size_t)i * 32 * Kk + koff);
            }
            cp_commit();
            cp_wait<1>();
        } else {
            cp_wait<0>();
        }
        __syncthreads();

        const uint32_t* Ab = As + buf * TILEW;
        const uint32_t* Bb = Bs + buf * TILEW;
        #pragma unroll
        for (int k8 = 0; k8 < 4; k8++) {
            int kb = k8 * 8;
            uint32_t bf[4][2];
            #pragma unroll
            for (int ni = 0; ni < 4; ni++) {
                int n = warpN * 32 + ni * 8 + g;
                bf[ni][0] = Bb[n * TSTR + kb + t];
                bf[ni][1] = Bb[n * TSTR + kb + t + 4];
            }
            #pragma unroll
            for (int mi = 0; mi < 4; mi++) {
                int m = warpM * 64 + mi * 16 + g;
                uint32_t af[4];
                af[0] = Ab[m * TSTR + kb + t];
                af[1] = Ab[(m + 8) * TSTR + kb + t];
                af[2] = Ab[m * TSTR + kb + t + 4];
                af[3] = Ab[(m + 8) * TSTR + kb + t + 4];
                #pragma unroll
                for (int ni = 0; ni < 4; ni++)
                    mma_tf32(acc[mi][ni], af, bf[ni]);
            }
        }
        __syncthreads();
    }

    #pragma unroll
    for (int mi = 0; mi < 4; mi++) {
        int r0 = m0 + warpM * 64 + mi * 16 + g;
        #pragma unroll
        for (int ni = 0; ni < 4; ni++) {
            int c = n0 + warpN * 32 + ni * 8 + 2 * t;
            size_t i0 = (size_t)r0 * Nn + c;
            size_t i1 = i0 + (size_t)8 * Nn;
            float2 v0 = make_float2(acc[mi][ni][0], acc[mi][ni][1]);
            float2 v1 = make_float2(acc[mi][ni][2], acc[mi][ni][3]);
            if (resid) {
                float2 r = *(const float2*)(resid + i0); v0.x += r.x; v0.y += r.y;
                r = *(const float2*)(resid + i1); v1.x += r.x; v1.y += r.y;
            }
            *(float2*)(C + i0) = v0;
            *(float2*)(C + i1) = v1;
        }
    }
}

// ---------------- expert tf32 GEMM (gathered rows, cp.async pipelined) ------
// mode 0: g_hidden[slot] = A@w1^T
// mode 1: g_hidden[slot] = silu(g_hidden[slot]) * (A@w3^T)
// mode 2: g_ypair[slot]  = A@w2^T
// grid (Nn/128, NTOK/128, E), block 256.
__global__ __launch_bounds__(256) void gemm_mma_expert(
    const float* __restrict__ A, int lda, int rowIsToken,
    const float* __restrict__ Wbase, int Kk, int Nn, int mode)
{
    const int e = blockIdx.z;
    const int count = g_expcnt[e];
    const int m0 = blockIdx.y * 128;
    if (m0 >= count) return;

    extern __shared__ uint32_t smbuf[];
    uint32_t* As = smbuf;
    uint32_t* Bs = smbuf + 2 * TILEW;
    __shared__ int srow[128];
    const uint32_t smA = (uint32_t)__cvta_generic_to_shared(As);
    const uint32_t smB = (uint32_t)__cvta_generic_to_shared(Bs);

    const int tid = threadIdx.x;
    if (tid < 128) {
        int r = m0 + tid;
        srow[tid] = (r < count) ? g_expslots[e * NTOK + r] : -1;
    }
    __syncthreads();

    const int lane = tid & 31, warp = tid >> 5;
    const int warpM = warp >> 2, warpN = warp & 3;
    const int g = lane >> 2, t = lane & 3;
    const int n0 = blockIdx.x * 128;
    const float* W = Wbase + (size_t)e * Nn * Kk;
    float acc[4][4][4] = {};

    const int lrow = tid >> 3;
    const int lkf = (tid & 7) * 4;

    // gathered row pointers (clamped; ok flag selects zero-fill)
    const float* arp[4];
    int aok[4];
    #pragma unroll
    for (int i = 0; i < 4; i++) {
        int s = srow[lrow + i * 32];
        aok[i] = (s >= 0);
        int arow = (s >= 0) ? (rowIsToken ? (s >> 1) : s) : 0;
        arp[i] = A + (size_t)arow * lda + lkf;
    }
    const float* Wp = W + (size_t)(n0 + lrow) * Kk + lkf;
    const uint32_t dA0 = smA + (lrow * TSTR + lkf) * 4;
    const uint32_t dB0 = smB + (lrow * TSTR + lkf) * 4;

    const int nt = Kk >> 5;
    #pragma unroll
    for (int i = 0; i < 4; i++) {
        cp16z(dA0 + i * 32 * TSTR * 4, arp[i], aok[i]);
        cp16(dB0 + i * 32 * TSTR * 4, Wp + (size_t)i * 32 * Kk);
    }
    cp_commit();

    for (int kt = 0; kt < nt; kt++) {
        const int buf = kt & 1;
        if (kt + 1 < nt) {
            const int koff = (kt + 1) * 32;
            const uint32_t bo = (buf ^ 1) * TILEW * 4;
            #pragma unroll
            for (int i = 0; i < 4; i++) {
                cp16z(dA0 + bo + i * 32 * TSTR * 4, arp[i] + koff, aok[i]);
                cp16(dB0 + bo + i * 32 * TSTR * 4, Wp + (size_t)i * 32 * Kk + koff);
            }
            cp_commit();
            cp_wait<1>();
        } else {
            cp_wait<0>();
        }
        __syncthreads();

        const uint32_t* Ab = As + buf * TILEW;
        const uint32_t* Bb = Bs + buf * TILEW;
        #pragma unroll
        for (int k8 = 0; k8 < 4; k8++) {
            int kb = k8 * 8;
            uint32_t bf[4][2];
            #pragma unroll
            for (int ni = 0; ni < 4; ni++) {
                int n = warpN * 32 + ni * 8 + g;
                bf[ni][0] = Bb[n * TSTR + kb + t];
                bf[ni][1] = Bb[n * TSTR + kb + t + 4];
            }
            #pragma unroll
            for (int mi = 0; mi < 4; mi++) {
                int m = warpM * 64 + mi * 16 + g;
                uint32_t af[4];
                af[0] = Ab[m * TSTR + kb + t];
                af[1] = Ab[(m + 8) * TSTR + kb + t];
                af[2] = Ab[m * TSTR + kb + t + 4];
                af[3] = Ab[(m + 8) * TSTR + kb + t + 4];
                #pragma unroll
                for (int ni = 0; ni < 4; ni++)
                    mma_tf32(acc[mi][ni], af, bf[ni]);
            }
        }
        __syncthreads();
    }

    #pragma unroll
    for (int mi = 0; mi < 4; mi++) {
        int mloc0 = warpM * 64 + mi * 16 + g;
        #pragma unroll
        for (int half = 0; half < 2; half++) {
            int mloc = mloc0 + half * 8;
            int s = srow[mloc];
            if (s < 0) continue;
            #pragma unroll
            for (int ni = 0; ni < 4; ni++) {
                int c = n0 + warpN * 32 + ni * 8 + 2 * t;
                float2 v = make_float2(acc[mi][ni][half * 2],
                                       acc[mi][ni][half * 2 + 1]);
                if (mode == 0) {
                    *(float2*)(&g_hidden[(size_t)s * FF + c]) = v;
                } else if (mode == 1) {
                    float2 h1 = *(const float2*)(&g_hidden[(size_t)s * FF + c]);
                    float2 o;
                    o.x = (h1.x / (1.f + expf(-h1.x))) * v.x;
                    o.y = (h1.y / (1.f + expf(-h1.y))) * v.y;
                    *(float2*)(&g_hidden[(size_t)s * FF + c]) = o;
                } else {
                    *(float2*)(&g_ypair[(size_t)s * DD + c]) = v;
                }
            }
        }
    }
}

// ---------------- RoPE (q and k in place) -----------------------------------
__global__ void rope_kernel(float* __restrict__ qh, float* __restrict__ kh,
                            const float* __restrict__ cosb,
                            const float* __restrict__ sinb)
{
    int idx = blockIdx.x * blockDim.x + threadIdx.x;
    int i = idx & 31;
    int th = idx >> 5;
    int t = th >> 4;
    int s = t & (SS - 1);
    float c = cosb[s * 32 + i], sn = sinb[s * 32 + i];
    size_t base = (size_t)th * HDD + i * 2;
    float xr = qh[base], xi = qh[base + 1];
    qh[base]     = xr * c - xi * sn;
    qh[base + 1] = xr * sn + xi * c;
    xr = kh[base]; xi = kh[base + 1];
    kh[base]     = xr * c - xi * sn;
    kh[base + 1] = xr * sn + xi * c;
}

// ---------------- Flash attention (fp32, 64x64 tiles) -----------------------
#define ATT_STRIDE 65
__global__ __launch_bounds__(256) void attn_kernel(
    const float* __restrict__ Q, const float* __restrict__ Kt,
    const float* __restrict__ V, float* __restrict__ O,
    const int* __restrict__ causal_flag)
{
    extern __shared__ float sm[];
    float* Qs = sm;
    float* Ks = Qs + 64 * ATT_STRIDE;
    float* Vs = Ks + 64 * ATT_STRIDE;
    float* Ps = Vs + 64 * ATT_STRIDE;
    const int qt = blockIdx.x;
    const int bh = blockIdx.y;
    const int b = bh >> 4, h = bh & 15;
    const int tid = threadIdx.x;
    const int lr = tid >> 2, lq = (tid & 3) * 16;
    const int causal = *causal_flag;
    const size_t headoff = (size_t)h * HDD;
    const float* Qb = Q + (size_t)b * SS * DD + headoff;
    const float* Kb = Kt + (size_t)b * SS * DD + headoff;
    const float* Vb = V + (size_t)b * SS * DD + headoff;

    {
        const float* src = Qb + (size_t)(qt * 64 + lr) * DD + lq;
        #pragma unroll
        for (int j4 = 0; j4 < 4; j4++) {
            float4 v = *(const float4*)(src + j4 * 4);
            Qs[lr * ATT_STRIDE + lq + j4 * 4 + 0] = v.x;
            Qs[lr * ATT_STRIDE + lq + j4 * 4 + 1] = v.y;
            Qs[lr * ATT_STRIDE + lq + j4 * 4 + 2] = v.z;
            Qs[lr * ATT_STRIDE + lq + j4 * 4 + 3] = v.w;
        }
    }

    const int r = tid >> 2, g = tid & 3;
    float m_run = -1e30f, l_run = 0.f;
    float Oacc[16];
    #pragma unroll
    for (int i = 0; i < 16; i++) Oacc[i] = 0.f;

    const int ktmax = causal ? qt : (SS / 64 - 1);
    for (int kt = 0; kt <= ktmax; kt++) {
        __syncthreads();
        {
            const float* ks = Kb + (size_t)(kt * 64 + lr) * DD + lq;
            const float* vs = Vb + (size_t)(kt * 64 + lr) * DD + lq;
            #pragma unroll
            for (int j4 = 0; j4 < 4; j4++) {
                float4 kv = *(const float4*)(ks + j4 * 4);
                float4 vv = *(const float4*)(vs + j4 * 4);
                int o = lr * ATT_STRIDE + lq + j4 * 4;
                Ks[o + 0] = kv.x; Ks[o + 1] = kv.y; Ks[o + 2] = kv.z; Ks[o + 3] = kv.w;
                Vs[o + 0] = vv.x; Vs[o + 1] = vv.y; Vs[o + 2] = vv.z; Vs[o + 3] = vv.w;
            }
        }
        __syncthreads();

        float sv[16];
        const float* qr = &Qs[r * ATT_STRIDE];
        #pragma unroll
        for (int cj = 0; cj < 16; cj++) {
            const float* kr = &Ks[(g * 16 + cj) * ATT_STRIDE];
            float sacc = 0.f;
            #pragma unroll
            for (int d = 0; d < 64; d++) sacc = fmaf(qr[d], kr[d], sacc);
            sv[cj] = sacc * ATT_SCALE;
        }
        if (causal && kt == qt) {
            #pragma unroll
            for (int cj = 0; cj < 16; cj++) {
                int c = g * 16 + cj;
                if (c > r) sv[cj] = -1e30f;
            }
        }
        float mloc = sv[0];
        #pragma unroll
        for (int cj = 1; cj < 16; cj++) mloc = fmaxf(mloc, sv[cj]);
        mloc = fmaxf(mloc, __shfl_xor_sync(0xffffffffu, mloc, 1));
        mloc = fmaxf(mloc, __shfl_xor_sync(0xffffffffu, mloc, 2));
        float m_new = fmaxf(m_run, mloc);
        float alpha = expf(m_run - m_new);
        float psum = 0.f;
        #pragma unroll
        for (int cj = 0; cj < 16; cj++) {
            float p = expf(sv[cj] - m_new);
            Ps[r * ATT_STRIDE + g * 16 + cj] = p;
            psum += p;
        }
        psum += __shfl_xor_sync(0xffffffffu, psum, 1);
        psum += __shfl_xor_sync(0xffffffffu, psum, 2);
        l_run = l_run * alpha + psum;
        m_run = m_new;
        __syncwarp();

        #pragma unroll
        for (int i = 0; i < 16; i++) Oacc[i] *= alpha;
        const float* pr = &Ps[r * ATT_STRIDE];
        for (int c = 0; c < 64; c++) {
            float p = pr[c];
            const float* vr = &Vs[c * ATT_STRIDE + g * 16];
            #pragma unroll
            for (int i = 0; i < 16; i++) Oacc[i] = fmaf(p, vr[i], Oacc[i]);
        }
    }

    float inv = 1.f / l_run;
    float* dst = O + (size_t)(b * SS + qt * 64 + r) * DD + headoff + g * 16;
    #pragma unroll
    for (int i = 0; i < 16; i++) dst[i] = Oacc[i] * inv;
}

// ---------------- router + top-2 --------------------------------------------
__global__ void zero_counts_kernel()
{
    if (threadIdx.x < EE) g_expcnt[threadIdx.x] = 0;
}

__global__ __launch_bounds__(256) void router_kernel(
    const float* __restrict__ xn, const float* __restrict__ rw,
    const float* __restrict__ rb)
{
    int t = blockIdx.x;
    float4 xv = ((const float4*)(xn + (size_t)t * DD))[threadIdx.x];
    float lg[EE];
    #pragma unroll
    for (int e = 0; e < EE; e++) {
        float4 wv = ((const float4*)(rw + (size_t)e * DD))[threadIdx.x];
        lg[e] = xv.x * wv.x + xv.y * wv.y + xv.z * wv.z + xv.w * wv.w;
    }
    #pragma unroll
    for (int o = 16; o; o >>= 1)
        #pragma unroll
        for (int e = 0; e < EE; e++)
            lg[e] += __shfl_xor_sync(0xffffffffu, lg[e], o);
    __shared__ float sh[EE][8];
    int warp = threadIdx.x >> 5;
    if ((threadIdx.x & 31) == 0)
        #pragma unroll
        for (int e = 0; e < EE; e++) sh[e][warp] = lg[e];
    __syncthreads();
    if (threadIdx.x == 0) {
        float logits[EE];
        #pragma unroll
        for (int e = 0; e < EE; e++) {
            float s = rb[e];
            #pragma unroll
            for (int w = 0; w < 8; w++) s += sh[e][w];
            logits[e] = s;
        }
        int i0 = 0;
        #pragma unroll
        for (int e = 1; e < EE; e++) if (logits[e] > logits[i0]) i0 = e;
        int i1 = -1;
        #pragma unroll
        for (int e = 0; e < EE; e++)
            if (e != i0 && (i1 < 0 || logits[e] > logits[i1])) i1 = e;
        float ex = expf(logits[i1] - logits[i0]);
        float denom = 1.f + ex;
        float p0 = 1.f / denom, p1 = ex / denom;
        int s0 = atomicAdd(&g_expcnt[i0], 1);
        g_expslots[i0 * NTOK + s0] = 2 * t;
        g_gate[2 * t] = p0;
        int s1 = atomicAdd(&g_expcnt[i1], 1);
        g_expslots[i1 * NTOK + s1] = 2 * t + 1;
        g_gate[2 * t + 1] = p1;
    }
}

// ---------------- final combine ---------------------------------------------
__global__ __launch_bounds__(256) void combine_kernel(float* __restrict__ out)
{
    int idx = blockIdx.x * 256 + threadIdx.x;
    int t = idx >> 8;
    int col = idx & 255;
    float g0 = g_gate[2 * t], g1 = g_gate[2 * t + 1];
    float4 hv = ((const float4*)g_h)[idx];
    float4 y0 = ((const float4*)g_ypair)[(size_t)(2 * t) * 256 + col];
    float4 y1 = ((const float4*)g_ypair)[(size_t)(2 * t + 1) * 256 + col];
    float4 o;
    o.x = hv.x + g0 * y0.x + g1 * y1.x;
    o.y = hv.y + g0 * y0.y + g1 * y1.y;
    o.z = hv.z + g0 * y0.z + g1 * y1.z;
    o.w = hv.w + g0 * y0.w + g1 * y1.w;
    ((float4*)out)[idx] = o;
}

// ---------------- launch ----------------------------------------------------
extern "C" void kernel_launch(void* const* d_in, const int* in_sizes, int n_in,
                              void* d_out, int out_size)
{
    const float* q     = (const float*)d_in[0];
    const float* fcos  = (const float*)d_in[3];
    const float* fsin  = (const float*)d_in[4];
    const float* att_w = (const float*)d_in[5];
    const float* ffn_w = (const float*)d_in[6];
    const float* wq    = (const float*)d_in[7];
    const float* wk    = (const float*)d_in[8];
    const float* wv    = (const float*)d_in[9];
    const float* wo    = (const float*)d_in[10];
    const float* rw    = (const float*)d_in[11];
    const float* rb    = (const float*)d_in[12];
    const float* w1    = (const float*)d_in[13];
    const float* w2    = (const float*)d_in[14];
    const float* w3    = (const float*)d_in[15];
    const int*   causal= (const int*)d_in[16];
    float* out = (float*)d_out;

    float *p_xn, *p_qh, *p_kh, *p_vh, *p_att, *p_h, *p_hidden;
    cudaGetSymbolAddress((void**)&p_xn, g_xn);
    cudaGetSymbolAddress((void**)&p_qh, g_qh);
    cudaGetSymbolAddress((void**)&p_kh, g_kh);
    cudaGetSymbolAddress((void**)&p_vh, g_vh);
    cudaGetSymbolAddress((void**)&p_att, g_att);
    cudaGetSymbolAddress((void**)&p_h, g_h);
    cudaGetSymbolAddress((void**)&p_hidden, g_hidden);

    const size_t attn_smem = 4 * 64 * ATT_STRIDE * sizeof(float);
    cudaFuncSetAttribute(attn_kernel,
                         cudaFuncAttributeMaxDynamicSharedMemorySize,
                         (int)attn_smem);
    cudaFuncSetAttribute(gemm_mma_proj,
                         cudaFuncAttributeMaxDynamicSharedMemorySize,
                         GEMM_SMEM);
    cudaFuncSetAttribute(gemm_mma_expert,
                         cudaFuncAttributeMaxDynamicSharedMemorySize,
                         GEMM_SMEM);

    // 1. qn = rmsnorm(q) * att_norm_w
    rmsnorm_kernel<<<NTOK, 256>>>(q, att_w, p_xn);

    // 2. QKV projections (tf32 tensor cores, pipelined)
    dim3 gproj(DD / 128, NTOK / 128);
    gemm_mma_proj<<<gproj, 256, GEMM_SMEM>>>(p_xn, wq, nullptr, p_qh, DD, DD);
    gemm_mma_proj<<<gproj, 256, GEMM_SMEM>>>(p_xn, wk, nullptr, p_kh, DD, DD);
    gemm_mma_proj<<<gproj, 256, GEMM_SMEM>>>(p_xn, wv, nullptr, p_vh, DD, DD);

    // 3. RoPE
    rope_kernel<<<(NTOK * HH * (HDD / 2)) / 256, 256>>>(p_qh, p_kh, fcos, fsin);

    // 4. flash attention
    attn_kernel<<<dim3(SS / 64, BB * HH), 256, attn_smem>>>(p_qh, p_kh, p_vh, p_att, causal);

    // 5. h = q + att @ wo^T
    gemm_mma_proj<<<gproj, 256, GEMM_SMEM>>>(p_att, wo, q, p_h, DD, DD);

    // 6. hn = rmsnorm(h)
    rmsnorm_kernel<<<NTOK, 256>>>(p_h, ffn_w, p_xn);

    // 7. routing
    zero_counts_kernel<<<1, 32>>>();
    router_kernel<<<NTOK, 256>>>(p_xn, rw, rb);

    // 8. MoE expert GEMMs (tf32 tensor cores, sparse slot lists, pipelined)
    dim3 g1(FF / 128, NTOK / 128, EE);
    gemm_mma_expert<<<g1, 256, GEMM_SMEM>>>(p_xn, DD, 1, w1, DD, FF, 0);
    gemm_mma_expert<<<g1, 256, GEMM_SMEM>>>(p_xn, DD, 1, w3, DD, FF, 1);
    dim3 g2(DD / 128, NTOK / 128, EE);
    gemm_mma_expert<<<g2, 256, GEMM_SMEM>>>(p_hidden, FF, 0, w2, FF, DD, 2);

    // 9. combine
    combine_kernel<<<NTOK, 256>>>(out);
}

// round 6
// speedup vs baseline: 2.5798x; 1.0656x over previous
#include <cuda_runtime.h>
#include <math.h>
#include <stdint.h>

// Problem constants
#define BB 4
#define SS 1024
#define DD 1024
#define HH 16
#define HDD 64
#define EE 8
#define FF 4096
#define NTOK 4096      // B*S
#define NSLOT 8192     // NTOK * K(=2)
#define RMS_EPS 1e-6f
#define ATT_SCALE 0.125f   // 1/sqrt(64)

// ---------------- scratch (static device globals; no runtime allocation) ----
__device__ float g_xn[NTOK * DD];
__device__ float g_qh[NTOK * DD];
__device__ float g_kh[NTOK * DD];
__device__ float g_vh[NTOK * DD];
__device__ float g_att[NTOK * DD];
__device__ float g_h[NTOK * DD];
__device__ float g_hidden[(size_t)NSLOT * FF];
__device__ float g_ypair[(size_t)NSLOT * DD];
__device__ float g_gate[NSLOT];
__device__ int   g_expcnt[EE];
__device__ int   g_expslots[EE * NTOK];

// ---------------- helpers ---------------------------------------------------
__device__ __forceinline__ void mma_tf32(float* c, const uint32_t* a, const uint32_t* b) {
    asm volatile(
        "mma.sync.aligned.m16n8k8.row.col.f32.tf32.tf32.f32 "
        "{%0,%1,%2,%3}, {%4,%5,%6,%7}, {%8,%9}, {%0,%1,%2,%3};\n"
        : "+f"(c[0]), "+f"(c[1]), "+f"(c[2]), "+f"(c[3])
        : "r"(a[0]), "r"(a[1]), "r"(a[2]), "r"(a[3]), "r"(b[0]), "r"(b[1]));
}

__device__ __forceinline__ void cp16(uint32_t dst, const void* src) {
    asm volatile("cp.async.cg.shared.global [%0], [%1], 16;\n"
                 :: "r"(dst), "l"(src));
}
__device__ __forceinline__ void cp16z(uint32_t dst, const void* src, int ok) {
    asm volatile("cp.async.cg.shared.global [%0], [%1], 16, %2;\n"
                 :: "r"(dst), "l"(src), "r"(ok ? 16 : 0));
}
__device__ __forceinline__ void cp_commit() {
    asm volatile("cp.async.commit_group;\n" ::: "memory");
}
template <int N>
__device__ __forceinline__ void cp_wait() {
    asm volatile("cp.async.wait_group %0;\n" :: "n"(N) : "memory");
}

// Smem tiles: 128x32 (A / full-width B) and 64x32 (half-width B), stride 36.
#define TSTR 36
#define TILEW (128 * TSTR)                    // uint32 per 128-row tile
#define TILEB (64 * TSTR)                     // uint32 per 64-row tile
#define GEMM_SMEM  (4 * TILEW * 4)            // S=2 x (A + B128)      = 73728 B
#define PROJ_SMEM  (6 * TILEW * 4)            // S=3 x (A + B128)      = 110592 B
#define W13_SMEM   ((2 * TILEW + 4 * TILEB) * 4)  // S=2 x (A + 2xB64) = 73728 B

// ---------------- RMSNorm ---------------------------------------------------
__global__ __launch_bounds__(256) void rmsnorm_kernel(
    const float* __restrict__ x, const float* __restrict__ w,
    float* __restrict__ out)
{
    int t = blockIdx.x;
    const float4* xr = (const float4*)(x + (size_t)t * DD);
    float4 v = xr[threadIdx.x];
    float ss = v.x * v.x + v.y * v.y + v.z * v.z + v.w * v.w;
    #pragma unroll
    for (int o = 16; o; o >>= 1) ss += __shfl_xor_sync(0xffffffffu, ss, o);
    __shared__ float sh[8];
    __shared__ float stot;
    int warp = threadIdx.x >> 5;
    if ((threadIdx.x & 31) == 0) sh[warp] = ss;
    __syncthreads();
    if (threadIdx.x == 0) {
        float s = 0.f;
        #pragma unroll
        for (int i = 0; i < 8; i++) s += sh[i];
        stot = rsqrtf(s / (float)DD + RMS_EPS);
    }
    __syncthreads();
    float sc = stot;
    float4 wv = ((const float4*)w)[threadIdx.x];
    float4 o;
    o.x = v.x * sc * wv.x; o.y = v.y * sc * wv.y;
    o.z = v.z * sc * wv.z; o.w = v.w * sc * wv.w;
    ((float4*)(out + (size_t)t * DD))[threadIdx.x] = o;
}

// ---- 3-stage issue macro for dense proj (A + B 128-row tiles) --------------
#define ISSUE_PROJ(tile, st) do {                                              \
    const int koff_ = (tile) * 32;                                             \
    const uint32_t ao_ = (uint32_t)(st) * TILEW * 4;                           \
    _Pragma("unroll")                                                          \
    for (int i_ = 0; i_ < 4; i_++) {                                           \
        cp16(dA0 + ao_ + i_ * 32 * TSTR * 4, Ap + (size_t)i_ * 32 * Kk + koff_); \
        cp16(dB0 + ao_ + i_ * 32 * TSTR * 4, Wp + (size_t)i_ * 32 * Kk + koff_); \
    }                                                                          \
    cp_commit();                                                               \
} while (0)

// Shared compute step for 128x128 tile (acc[4][4][4])
#define COMPUTE_TILE(Ab, Bb)                                                   \
    _Pragma("unroll")                                                          \
    for (int k8 = 0; k8 < 4; k8++) {                                           \
        int kb = k8 * 8;                                                       \
        uint32_t bf[4][2];                                                     \
        _Pragma("unroll")                                                      \
        for (int ni = 0; ni < 4; ni++) {                                       \
            int n = warpN * 32 + ni * 8 + g;                                   \
            bf[ni][0] = (Bb)[n * TSTR + kb + t];                               \
            bf[ni][1] = (Bb)[n * TSTR + kb + t + 4];                           \
        }                                                                      \
        _Pragma("unroll")                                                      \
        for (int mi = 0; mi < 4; mi++) {                                       \
            int m = warpM * 64 + mi * 16 + g;                                  \
            uint32_t af[4];                                                    \
            af[0] = (Ab)[m * TSTR + kb + t];                                   \
            af[1] = (Ab)[(m + 8) * TSTR + kb + t];                             \
            af[2] = (Ab)[m * TSTR + kb + t + 4];                               \
            af[3] = (Ab)[(m + 8) * TSTR + kb + t + 4];                         \
            _Pragma("unroll")                                                  \
            for (int ni = 0; ni < 4; ni++)                                     \
                mma_tf32(acc[mi][ni], af, bf[ni]);                             \
        }                                                                      \
    }

// ---------------- dense proj GEMM, 3-stage pipeline, 1 barrier/tile ---------
// C[M,N] = A[M,K] @ W[N,K]^T (+resid). grid (N/128, M/128), block 256.
__global__ __launch_bounds__(256) void gemm_mma_proj3(
    const float* __restrict__ A, const float* __restrict__ W,
    const float* __restrict__ resid, float* __restrict__ C,
    int Kk, int Nn)
{
    extern __shared__ uint32_t smbuf[];
    uint32_t* As = smbuf;                  // [3][TILEW]
    uint32_t* Bs = smbuf + 3 * TILEW;      // [3][TILEW]
    const uint32_t smA = (uint32_t)__cvta_generic_to_shared(As);
    const uint32_t smB = (uint32_t)__cvta_generic_to_shared(Bs);

    const int tid = threadIdx.x;
    const int lane = tid & 31, warp = tid >> 5;
    const int warpM = warp >> 2, warpN = warp & 3;
    const int g = lane >> 2, t = lane & 3;
    const int m0 = blockIdx.y * 128, n0 = blockIdx.x * 128;
    float acc[4][4][4] = {};

    const int lrow = tid >> 3;
    const int lkf = (tid & 7) * 4;
    const float* Ap = A + (size_t)(m0 + lrow) * Kk + lkf;
    const float* Wp = W + (size_t)(n0 + lrow) * Kk + lkf;
    const uint32_t dA0 = smA + (lrow * TSTR + lkf) * 4;
    const uint32_t dB0 = smB + (lrow * TSTR + lkf) * 4;

    const int nt = Kk >> 5;
    ISSUE_PROJ(0, 0);
    ISSUE_PROJ(1, 1);

    for (int kt = 0; kt < nt; kt++) {
        if (kt + 1 < nt) cp_wait<1>(); else cp_wait<0>();
        __syncthreads();
        if (kt + 2 < nt) {
            ISSUE_PROJ(kt + 2, (kt + 2) % 3);
        }
        const uint32_t* Ab = As + (kt % 3) * TILEW;
        const uint32_t* Bb = Bs + (kt % 3) * TILEW;
        COMPUTE_TILE(Ab, Bb);
    }

    #pragma unroll
    for (int mi = 0; mi < 4; mi++) {
        int r0 = m0 + warpM * 64 + mi * 16 + g;
        #pragma unroll
        for (int ni = 0; ni < 4; ni++) {
            int c = n0 + warpN * 32 + ni * 8 + 2 * t;
            size_t i0 = (size_t)r0 * Nn + c;
            size_t i1 = i0 + (size_t)8 * Nn;
            float2 v0 = make_float2(acc[mi][ni][0], acc[mi][ni][1]);
            float2 v1 = make_float2(acc[mi][ni][2], acc[mi][ni][3]);
            if (resid) {
                float2 r = *(const float2*)(resid + i0); v0.x += r.x; v0.y += r.y;
                r = *(const float2*)(resid + i1); v1.x += r.x; v1.y += r.y;
            }
            *(float2*)(C + i0) = v0;
            *(float2*)(C + i1) = v1;
        }
    }
}

// ---------------- fused QKV projection (3 weight mats, one grid) ------------
// grid (3*DD/128 = 24, NTOK/128), block 256. CTA selects wq/wk/wv by n-tile.
__global__ __launch_bounds__(256) void gemm_mma_qkv(
    const float* __restrict__ A,
    const float* __restrict__ wq, const float* __restrict__ wk,
    const float* __restrict__ wv,
    float* __restrict__ qo, float* __restrict__ ko, float* __restrict__ vo)
{
    extern __shared__ uint32_t smbuf[];
    uint32_t* As = smbuf;
    uint32_t* Bs = smbuf + 3 * TILEW;
    const uint32_t smA = (uint32_t)__cvta_generic_to_shared(As);
    const uint32_t smB = (uint32_t)__cvta_generic_to_shared(Bs);

    const int tid = threadIdx.x;
    const int lane = tid & 31, warp = tid >> 5;
    const int warpM = warp >> 2, warpN = warp & 3;
    const int g = lane >> 2, t = lane & 3;
    const int m0 = blockIdx.y * 128;
    const int n0t = blockIdx.x * 128;

    const float* W; float* C; int n0;
    if (n0t < DD)            { W = wq; C = qo; n0 = n0t; }
    else if (n0t < 2 * DD)   { W = wk; C = ko; n0 = n0t - DD; }
    else                     { W = wv; C = vo; n0 = n0t - 2 * DD; }

    const int Kk = DD;
    float acc[4][4][4] = {};

    const int lrow = tid >> 3;
    const int lkf = (tid & 7) * 4;
    const float* Ap = A + (size_t)(m0 + lrow) * Kk + lkf;
    const float* Wp = W + (size_t)(n0 + lrow) * Kk + lkf;
    const uint32_t dA0 = smA + (lrow * TSTR + lkf) * 4;
    const uint32_t dB0 = smB + (lrow * TSTR + lkf) * 4;

    const int nt = Kk >> 5;
    ISSUE_PROJ(0, 0);
    ISSUE_PROJ(1, 1);

    for (int kt = 0; kt < nt; kt++) {
        if (kt + 1 < nt) cp_wait<1>(); else cp_wait<0>();
        __syncthreads();
        if (kt + 2 < nt) {
            ISSUE_PROJ(kt + 2, (kt + 2) % 3);
        }
        const uint32_t* Ab = As + (kt % 3) * TILEW;
        const uint32_t* Bb = Bs + (kt % 3) * TILEW;
        COMPUTE_TILE(Ab, Bb);
    }

    #pragma unroll
    for (int mi = 0; mi < 4; mi++) {
        int r0 = m0 + warpM * 64 + mi * 16 + g;
        #pragma unroll
        for (int ni = 0; ni < 4; ni++) {
            int c = n0 + warpN * 32 + ni * 8 + 2 * t;
            size_t i0 = (size_t)r0 * DD + c;
            size_t i1 = i0 + (size_t)8 * DD;
            *(float2*)(C + i0) = make_float2(acc[mi][ni][0], acc[mi][ni][1]);
            *(float2*)(C + i1) = make_float2(acc[mi][ni][2], acc[mi][ni][3]);
        }
    }
}

// ---------------- fused w1+w3 expert GEMM -----------------------------------
// hidden[slot, n] = silu(A@w1^T) * (A@w3^T), both computed in one CTA.
// CTA tile: 128 slots x 64 F-cols (per B). grid (FF/64, NTOK/128, E), block 256.
// Warp grid 2(M) x 4(N): warp tile 64x16 per B.
__global__ __launch_bounds__(256) void gemm_mma_w13(
    const float* __restrict__ A,
    const float* __restrict__ W1base, const float* __restrict__ W3base)
{
    const int e = blockIdx.z;
    const int count = g_expcnt[e];
    const int m0 = blockIdx.y * 128;
    if (m0 >= count) return;

    extern __shared__ uint32_t smbuf[];
    uint32_t* As  = smbuf;                          // [2][TILEW]
    uint32_t* B1s = smbuf + 2 * TILEW;              // [2][TILEB]
    uint32_t* B3s = smbuf + 2 * TILEW + 2 * TILEB;  // [2][TILEB]
    __shared__ int srow[128];
    const uint32_t smA  = (uint32_t)__cvta_generic_to_shared(As);
    const uint32_t smB1 = (uint32_t)__cvta_generic_to_shared(B1s);
    const uint32_t smB3 = (uint32_t)__cvta_generic_to_shared(B3s);

    const int tid = threadIdx.x;
    if (tid < 128) {
        int r = m0 + tid;
        srow[tid] = (r < count) ? g_expslots[e * NTOK + r] : -1;
    }
    __syncthreads();

    const int lane = tid & 31, warp = tid >> 5;
    const int warpM = warp >> 2, warpN = warp & 3;
    const int g = lane >> 2, t = lane & 3;
    const int n0 = blockIdx.x * 64;
    const float* W1 = W1base + (size_t)e * FF * DD;
    const float* W3 = W3base + (size_t)e * FF * DD;
    float acc1[4][2][4] = {};
    float acc3[4][2][4] = {};

    const int lrow = tid >> 3;
    const int lkf = (tid & 7) * 4;

    const float* arp[4];
    int aok[4];
    #pragma unroll
    for (int i = 0; i < 4; i++) {
        int s = srow[lrow + i * 32];
        aok[i] = (s >= 0);
        int arow = (s >= 0) ? (s >> 1) : 0;     // slot -> token
        arp[i] = A + (size_t)arow * DD + lkf;
    }
    const float* Wp1 = W1 + (size_t)(n0 + lrow) * DD + lkf;
    const float* Wp3 = W3 + (size_t)(n0 + lrow) * DD + lkf;
    const uint32_t dA0  = smA  + (lrow * TSTR + lkf) * 4;
    const uint32_t dB10 = smB1 + (lrow * TSTR + lkf) * 4;
    const uint32_t dB30 = smB3 + (lrow * TSTR + lkf) * 4;

    const int nt = DD >> 5;   // 32
    // prologue
    #pragma unroll
    for (int i = 0; i < 4; i++)
        cp16z(dA0 + i * 32 * TSTR * 4, arp[i], aok[i]);
    #pragma unroll
    for (int i = 0; i < 2; i++) {
        cp16(dB10 + i * 32 * TSTR * 4, Wp1 + (size_t)i * 32 * DD);
        cp16(dB30 + i * 32 * TSTR * 4, Wp3 + (size_t)i * 32 * DD);
    }
    cp_commit();

    for (int kt = 0; kt < nt; kt++) {
        const int buf = kt & 1;
        if (kt + 1 < nt) {
            const int koff = (kt + 1) * 32;
            const uint32_t aoW = (uint32_t)(buf ^ 1) * TILEW * 4;
            const uint32_t aoB = (uint32_t)(buf ^ 1) * TILEB * 4;
            #pragma unroll
            for (int i = 0; i < 4; i++)
                cp16z(dA0 + aoW + i * 32 * TSTR * 4, arp[i] + koff, aok[i]);
            #pragma unroll
            for (int i = 0; i < 2; i++) {
                cp16(dB10 + aoB + i * 32 * TSTR * 4, Wp1 + (size_t)i * 32 * DD + koff);
                cp16(dB30 + aoB + i * 32 * TSTR * 4, Wp3 + (size_t)i * 32 * DD + koff);
            }
            cp_commit();
            cp_wait<1>();
        } else {
            cp_wait<0>();
        }
        __syncthreads();

        const uint32_t* Ab  = As  + buf * TILEW;
        const uint32_t* B1b = B1s + buf * TILEB;
        const uint32_t* B3b = B3s + buf * TILEB;
        #pragma unroll
        for (int k8 = 0; k8 < 4; k8++) {
            int kb = k8 * 8;
            uint32_t bf1[2][2], bf3[2][2];
            #pragma unroll
            for (int ni = 0; ni < 2; ni++) {
                int n = warpN * 16 + ni * 8 + g;
                bf1[ni][0] = B1b[n * TSTR + kb + t];
                bf1[ni][1] = B1b[n * TSTR + kb + t + 4];
                bf3[ni][0] = B3b[n * TSTR + kb + t];
                bf3[ni][1] = B3b[n * TSTR + kb + t + 4];
            }
            #pragma unroll
            for (int mi = 0; mi < 4; mi++) {
                int m = warpM * 64 + mi * 16 + g;
                uint32_t af[4];
                af[0] = Ab[m * TSTR + kb + t];
                af[1] = Ab[(m + 8) * TSTR + kb + t];
                af[2] = Ab[m * TSTR + kb + t + 4];
                af[3] = Ab[(m + 8) * TSTR + kb + t + 4];
                #pragma unroll
                for (int ni = 0; ni < 2; ni++) {
                    mma_tf32(acc1[mi][ni], af, bf1[ni]);
                    mma_tf32(acc3[mi][ni], af, bf3[ni]);
                }
            }
        }
        __syncthreads();
    }

    // epilogue: hidden = silu(h1) * h3, written once
    #pragma unroll
    for (int mi = 0; mi < 4; mi++) {
        int mloc0 = warpM * 64 + mi * 16 + g;
        #pragma unroll
        for (int half = 0; half < 2; half++) {
            int mloc = mloc0 + half * 8;
            int s = srow[mloc];
            if (s < 0) continue;
            #pragma unroll
            for (int ni = 0; ni < 2; ni++) {
                int c = n0 + warpN * 16 + ni * 8 + 2 * t;
                float h1x = acc1[mi][ni][half * 2],     h1y = acc1[mi][ni][half * 2 + 1];
                float h3x = acc3[mi][ni][half * 2],     h3y = acc3[mi][ni][half * 2 + 1];
                float2 o;
                o.x = (h1x / (1.f + expf(-h1x))) * h3x;
                o.y = (h1y / (1.f + expf(-h1y))) * h3y;
                *(float2*)(&g_hidden[(size_t)s * FF + c]) = o;
            }
        }
    }
}

// ---------------- w2 expert GEMM (gathered hidden rows, S=2) ----------------
// g_ypair[slot] = hidden[slot] @ w2^T. grid (DD/128, NTOK/128, E), block 256.
__global__ __launch_bounds__(256) void gemm_mma_w2(
    const float* __restrict__ A, const float* __restrict__ Wbase)
{
    const int e = blockIdx.z;
    const int count = g_expcnt[e];
    const int m0 = blockIdx.y * 128;
    if (m0 >= count) return;

    extern __shared__ uint32_t smbuf[];
    uint32_t* As = smbuf;
    uint32_t* Bs = smbuf + 2 * TILEW;
    __shared__ int srow[128];
    const uint32_t smA = (uint32_t)__cvta_generic_to_shared(As);
    const uint32_t smB = (uint32_t)__cvta_generic_to_shared(Bs);

    const int tid = threadIdx.x;
    if (tid < 128) {
        int r = m0 + tid;
        srow[tid] = (r < count) ? g_expslots[e * NTOK + r] : -1;
    }
    __syncthreads();

    const int lane = tid & 31, warp = tid >> 5;
    const int warpM = warp >> 2, warpN = warp & 3;
    const int g = lane >> 2, t = lane & 3;
    const int n0 = blockIdx.x * 128;
    const float* W = Wbase + (size_t)e * DD * FF;
    const int Kk = FF;
    float acc[4][4][4] = {};

    const int lrow = tid >> 3;
    const int lkf = (tid & 7) * 4;

    const float* arp[4];
    int aok[4];
    #pragma unroll
    for (int i = 0; i < 4; i++) {
        int s = srow[lrow + i * 32];
        aok[i] = (s >= 0);
        int arow = (s >= 0) ? s : 0;
        arp[i] = A + (size_t)arow * FF + lkf;
    }
    const float* Wp = W + (size_t)(n0 + lrow) * Kk + lkf;
    const uint32_t dA0 = smA + (lrow * TSTR + lkf) * 4;
    const uint32_t dB0 = smB + (lrow * TSTR + lkf) * 4;

    const int nt = Kk >> 5;
    #pragma unroll
    for (int i = 0; i < 4; i++) {
        cp16z(dA0 + i * 32 * TSTR * 4, arp[i], aok[i]);
        cp16(dB0 + i * 32 * TSTR * 4, Wp + (size_t)i * 32 * Kk);
    }
    cp_commit();

    for (int kt = 0; kt < nt; kt++) {
        const int buf = kt & 1;
        if (kt + 1 < nt) {
            const int koff = (kt + 1) * 32;
            const uint32_t bo = (uint32_t)(buf ^ 1) * TILEW * 4;
            #pragma unroll
            for (int i = 0; i < 4; i++) {
                cp16z(dA0 + bo + i * 32 * TSTR * 4, arp[i] + koff, aok[i]);
                cp16(dB0 + bo + i * 32 * TSTR * 4, Wp + (size_t)i * 32 * Kk + koff);
            }
            cp_commit();
            cp_wait<1>();
        } else {
            cp_wait<0>();
        }
        __syncthreads();

        const uint32_t* Ab = As + buf * TILEW;
        const uint32_t* Bb = Bs + buf * TILEW;
        COMPUTE_TILE(Ab, Bb);
        __syncthreads();
    }

    #pragma unroll
    for (int mi = 0; mi < 4; mi++) {
        int mloc0 = warpM * 64 + mi * 16 + g;
        #pragma unroll
        for (int half = 0; half < 2; half++) {
            int mloc = mloc0 + half * 8;
            int s = srow[mloc];
            if (s < 0) continue;
            #pragma unroll
            for (int ni = 0; ni < 4; ni++) {
                int c = n0 + warpN * 32 + ni * 8 + 2 * t;
                *(float2*)(&g_ypair[(size_t)s * DD + c]) =
                    make_float2(acc[mi][ni][half * 2], acc[mi][ni][half * 2 + 1]);
            }
        }
    }
}

// ---------------- RoPE (q and k in place) -----------------------------------
__global__ void rope_kernel(float* __restrict__ qh, float* __restrict__ kh,
                            const float* __restrict__ cosb,
                            const float* __restrict__ sinb)
{
    int idx = blockIdx.x * blockDim.x + threadIdx.x;
    int i = idx & 31;
    int th = idx >> 5;
    int t = th >> 4;
    int s = t & (SS - 1);
    float c = cosb[s * 32 + i], sn = sinb[s * 32 + i];
    size_t base = (size_t)th * HDD + i * 2;
    float xr = qh[base], xi = qh[base + 1];
    qh[base]     = xr * c - xi * sn;
    qh[base + 1] = xr * sn + xi * c;
    xr = kh[base]; xi = kh[base + 1];
    kh[base]     = xr * c - xi * sn;
    kh[base + 1] = xr * sn + xi * c;
}

// ---------------- Flash attention (fp32, 64x64 tiles) -----------------------
#define ATT_STRIDE 65
__global__ __launch_bounds__(256) void attn_kernel(
    const float* __restrict__ Q, const float* __restrict__ Kt,
    const float* __restrict__ V, float* __restrict__ O,
    const int* __restrict__ causal_flag)
{
    extern __shared__ float sm[];
    float* Qs = sm;
    float* Ks = Qs + 64 * ATT_STRIDE;
    float* Vs = Ks + 64 * ATT_STRIDE;
    float* Ps = Vs + 64 * ATT_STRIDE;
    const int qt = blockIdx.x;
    const int bh = blockIdx.y;
    const int b = bh >> 4, h = bh & 15;
    const int tid = threadIdx.x;
    const int lr = tid >> 2, lq = (tid & 3) * 16;
    const int causal = *causal_flag;
    const size_t headoff = (size_t)h * HDD;
    const float* Qb = Q + (size_t)b * SS * DD + headoff;
    const float* Kb = Kt + (size_t)b * SS * DD + headoff;
    const float* Vb = V + (size_t)b * SS * DD + headoff;

    {
        const float* src = Qb + (size_t)(qt * 64 + lr) * DD + lq;
        #pragma unroll
        for (int j4 = 0; j4 < 4; j4++) {
            float4 v = *(const float4*)(src + j4 * 4);
            Qs[lr * ATT_STRIDE + lq + j4 * 4 + 0] = v.x;
            Qs[lr * ATT_STRIDE + lq + j4 * 4 + 1] = v.y;
            Qs[lr * ATT_STRIDE + lq + j4 * 4 + 2] = v.z;
            Qs[lr * ATT_STRIDE + lq + j4 * 4 + 3] = v.w;
        }
    }

    const int r = tid >> 2, g = tid & 3;
    float m_run = -1e30f, l_run = 0.f;
    float Oacc[16];
    #pragma unroll
    for (int i = 0; i < 16; i++) Oacc[i] = 0.f;

    const int ktmax = causal ? qt : (SS / 64 - 1);
    for (int kt = 0; kt <= ktmax; kt++) {
        __syncthreads();
        {
            const float* ks = Kb + (size_t)(kt * 64 + lr) * DD + lq;
            const float* vs = Vb + (size_t)(kt * 64 + lr) * DD + lq;
            #pragma unroll
            for (int j4 = 0; j4 < 4; j4++) {
                float4 kv = *(const float4*)(ks + j4 * 4);
                float4 vv = *(const float4*)(vs + j4 * 4);
                int o = lr * ATT_STRIDE + lq + j4 * 4;
                Ks[o + 0] = kv.x; Ks[o + 1] = kv.y; Ks[o + 2] = kv.z; Ks[o + 3] = kv.w;
                Vs[o + 0] = vv.x; Vs[o + 1] = vv.y; Vs[o + 2] = vv.z; Vs[o + 3] = vv.w;
            }
        }
        __syncthreads();

        float sv[16];
        const float* qr = &Qs[r * ATT_STRIDE];
        #pragma unroll
        for (int cj = 0; cj < 16; cj++) {
            const float* kr = &Ks[(g * 16 + cj) * ATT_STRIDE];
            float sacc = 0.f;
            #pragma unroll
            for (int d = 0; d < 64; d++) sacc = fmaf(qr[d], kr[d], sacc);
            sv[cj] = sacc * ATT_SCALE;
        }
        if (causal && kt == qt) {
            #pragma unroll
            for (int cj = 0; cj < 16; cj++) {
                int c = g * 16 + cj;
                if (c > r) sv[cj] = -1e30f;
            }
        }
        float mloc = sv[0];
        #pragma unroll
        for (int cj = 1; cj < 16; cj++) mloc = fmaxf(mloc, sv[cj]);
        mloc = fmaxf(mloc, __shfl_xor_sync(0xffffffffu, mloc, 1));
        mloc = fmaxf(mloc, __shfl_xor_sync(0xffffffffu, mloc, 2));
        float m_new = fmaxf(m_run, mloc);
        float alpha = expf(m_run - m_new);
        float psum = 0.f;
        #pragma unroll
        for (int cj = 0; cj < 16; cj++) {
            float p = expf(sv[cj] - m_new);
            Ps[r * ATT_STRIDE + g * 16 + cj] = p;
            psum += p;
        }
        psum += __shfl_xor_sync(0xffffffffu, psum, 1);
        psum += __shfl_xor_sync(0xffffffffu, psum, 2);
        l_run = l_run * alpha + psum;
        m_run = m_new;
        __syncwarp();

        #pragma unroll
        for (int i = 0; i < 16; i++) Oacc[i] *= alpha;
        const float* pr = &Ps[r * ATT_STRIDE];
        for (int c = 0; c < 64; c++) {
            float p = pr[c];
            const float* vr = &Vs[c * ATT_STRIDE + g * 16];
            #pragma unroll
            for (int i = 0; i < 16; i++) Oacc[i] = fmaf(p, vr[i], Oacc[i]);
        }
    }

    float inv = 1.f / l_run;
    float* dst = O + (size_t)(b * SS + qt * 64 + r) * DD + headoff + g * 16;
    #pragma unroll
    for (int i = 0; i < 16; i++) dst[i] = Oacc[i] * inv;
}

// ---------------- router + top-2 --------------------------------------------
__global__ void zero_counts_kernel()
{
    if (threadIdx.x < EE) g_expcnt[threadIdx.x] = 0;
}

__global__ __launch_bounds__(256) void router_kernel(
    const float* __restrict__ xn, const float* __restrict__ rw,
    const float* __restrict__ rb)
{
    int t = blockIdx.x;
    float4 xv = ((const float4*)(xn + (size_t)t * DD))[threadIdx.x];
    float lg[EE];
    #pragma unroll
    for (int e = 0; e < EE; e++) {
        float4 wv = ((const float4*)(rw + (size_t)e * DD))[threadIdx.x];
        lg[e] = xv.x * wv.x + xv.y * wv.y + xv.z * wv.z + xv.w * wv.w;
    }
    #pragma unroll
    for (int o = 16; o; o >>= 1)
        #pragma unroll
        for (int e = 0; e < EE; e++)
            lg[e] += __shfl_xor_sync(0xffffffffu, lg[e], o);
    __shared__ float sh[EE][8];
    int warp = threadIdx.x >> 5;
    if ((threadIdx.x & 31) == 0)
        #pragma unroll
        for (int e = 0; e < EE; e++) sh[e][warp] = lg[e];
    __syncthreads();
    if (threadIdx.x == 0) {
        float logits[EE];
        #pragma unroll
        for (int e = 0; e < EE; e++) {
            float s = rb[e];
            #pragma unroll
            for (int w = 0; w < 8; w++) s += sh[e][w];
            logits[e] = s;
        }
        int i0 = 0;
        #pragma unroll
        for (int e = 1; e < EE; e++) if (logits[e] > logits[i0]) i0 = e;
        int i1 = -1;
        #pragma unroll
        for (int e = 0; e < EE; e++)
            if (e != i0 && (i1 < 0 || logits[e] > logits[i1])) i1 = e;
        float ex = expf(logits[i1] - logits[i0]);
        float denom = 1.f + ex;
        float p0 = 1.f / denom, p1 = ex / denom;
        int s0 = atomicAdd(&g_expcnt[i0], 1);
        g_expslots[i0 * NTOK + s0] = 2 * t;
        g_gate[2 * t] = p0;
        int s1 = atomicAdd(&g_expcnt[i1], 1);
        g_expslots[i1 * NTOK + s1] = 2 * t + 1;
        g_gate[2 * t + 1] = p1;
    }
}

// ---------------- final combine ---------------------------------------------
__global__ __launch_bounds__(256) void combine_kernel(float* __restrict__ out)
{
    int idx = blockIdx.x * 256 + threadIdx.x;
    int t = idx >> 8;
    int col = idx & 255;
    float g0 = g_gate[2 * t], g1 = g_gate[2 * t + 1];
    float4 hv = ((const float4*)g_h)[idx];
    float4 y0 = ((const float4*)g_ypair)[(size_t)(2 * t) * 256 + col];
    float4 y1 = ((const float4*)g_ypair)[(size_t)(2 * t + 1) * 256 + col];
    float4 o;
    o.x = hv.x + g0 * y0.x + g1 * y1.x;
    o.y = hv.y + g0 * y0.y + g1 * y1.y;
    o.z = hv.z + g0 * y0.z + g1 * y1.z;
    o.w = hv.w + g0 * y0.w + g1 * y1.w;
    ((float4*)out)[idx] = o;
}

// ---------------- launch ----------------------------------------------------
extern "C" void kernel_launch(void* const* d_in, const int* in_sizes, int n_in,
                              void* d_out, int out_size)
{
    const float* q     = (const float*)d_in[0];
    const float* fcos  = (const float*)d_in[3];
    const float* fsin  = (const float*)d_in[4];
    const float* att_w = (const float*)d_in[5];
    const float* ffn_w = (const float*)d_in[6];
    const float* wq    = (const float*)d_in[7];
    const float* wk    = (const float*)d_in[8];
    const float* wv    = (const float*)d_in[9];
    const float* wo    = (const float*)d_in[10];
    const float* rw    = (const float*)d_in[11];
    const float* rb    = (const float*)d_in[12];
    const float* w1    = (const float*)d_in[13];
    const float* w2    = (const float*)d_in[14];
    const float* w3    = (const float*)d_in[15];
    const int*   causal= (const int*)d_in[16];
    float* out = (float*)d_out;

    float *p_xn, *p_qh, *p_kh, *p_vh, *p_att, *p_h, *p_hidden;
    cudaGetSymbolAddress((void**)&p_xn, g_xn);
    cudaGetSymbolAddress((void**)&p_qh, g_qh);
    cudaGetSymbolAddress((void**)&p_kh, g_kh);
    cudaGetSymbolAddress((void**)&p_vh, g_vh);
    cudaGetSymbolAddress((void**)&p_att, g_att);
    cudaGetSymbolAddress((void**)&p_h, g_h);
    cudaGetSymbolAddress((void**)&p_hidden, g_hidden);

    const size_t attn_smem = 4 * 64 * ATT_STRIDE * sizeof(float);
    cudaFuncSetAttribute(attn_kernel,
                         cudaFuncAttributeMaxDynamicSharedMemorySize, (int)attn_smem);
    cudaFuncSetAttribute(gemm_mma_proj3,
                         cudaFuncAttributeMaxDynamicSharedMemorySize, PROJ_SMEM);
    cudaFuncSetAttribute(gemm_mma_qkv,
                         cudaFuncAttributeMaxDynamicSharedMemorySize, PROJ_SMEM);
    cudaFuncSetAttribute(gemm_mma_w13,
                         cudaFuncAttributeMaxDynamicSharedMemorySize, W13_SMEM);
    cudaFuncSetAttribute(gemm_mma_w2,
                         cudaFuncAttributeMaxDynamicSharedMemorySize, GEMM_SMEM);

    // 1. qn = rmsnorm(q) * att_norm_w
    rmsnorm_kernel<<<NTOK, 256>>>(q, att_w, p_xn);

    // 2. fused QKV projection (one grid, 768 CTAs)
    gemm_mma_qkv<<<dim3(3 * DD / 128, NTOK / 128), 256, PROJ_SMEM>>>(
        p_xn, wq, wk, wv, p_qh, p_kh, p_vh);

    // 3. RoPE
    rope_kernel<<<(NTOK * HH * (HDD / 2)) / 256, 256>>>(p_qh, p_kh, fcos, fsin);

    // 4. flash attention
    attn_kernel<<<dim3(SS / 64, BB * HH), 256, attn_smem>>>(p_qh, p_kh, p_vh, p_att, causal);

    // 5. h = q + att @ wo^T
    gemm_mma_proj3<<<dim3(DD / 128, NTOK / 128), 256, PROJ_SMEM>>>(
        p_att, wo, q, p_h, DD, DD);

    // 6. hn = rmsnorm(h)
    rmsnorm_kernel<<<NTOK, 256>>>(p_h, ffn_w, p_xn);

    // 7. routing
    zero_counts_kernel<<<1, 32>>>();
    router_kernel<<<NTOK, 256>>>(p_xn, rw, rb);

    // 8. MoE: fused w1+w3 (writes silu(h1)*h3 once), then w2
    gemm_mma_w13<<<dim3(FF / 64, NTOK / 128, EE), 256, W13_SMEM>>>(p_xn, w1, w3);
    gemm_mma_w2<<<dim3(DD / 128, NTOK / 128, EE), 256, GEMM_SMEM>>>(p_hidden, w2);

    // 9. combine
    combine_kernel<<<NTOK, 256>>>(out);
}

// round 7
// speedup vs baseline: 3.8817x; 1.5046x over previous
#include <cuda_runtime.h>
#include <math.h>
#include <stdint.h>

// Problem constants
#define BB 4
#define SS 1024
#define DD 1024
#define HH 16
#define HDD 64
#define EE 8
#define FF 4096
#define NTOK 4096      // B*S
#define NSLOT 8192     // NTOK * K(=2)
#define RMS_EPS 1e-6f
#define ATT_SCALE 0.125f   // 1/sqrt(64)

// ---------------- scratch (static device globals; no runtime allocation) ----
__device__ float g_xn[NTOK * DD];
__device__ float g_qh[NTOK * DD];
__device__ float g_kh[NTOK * DD];
__device__ float g_vh[NTOK * DD];
__device__ float g_att[NTOK * DD];
__device__ float g_h[NTOK * DD];
__device__ float g_hidden[(size_t)NSLOT * FF];
__device__ float g_ypair[(size_t)NSLOT * DD];
__device__ float g_gate[NSLOT];
__device__ int   g_expcnt[EE];
__device__ int   g_expslots[EE * NTOK];

// ---------------- helpers ---------------------------------------------------
__device__ __forceinline__ void mma_tf32(float* c, const uint32_t* a, const uint32_t* b) {
    asm volatile(
        "mma.sync.aligned.m16n8k8.row.col.f32.tf32.tf32.f32 "
        "{%0,%1,%2,%3}, {%4,%5,%6,%7}, {%8,%9}, {%0,%1,%2,%3};\n"
        : "+f"(c[0]), "+f"(c[1]), "+f"(c[2]), "+f"(c[3])
        : "r"(a[0]), "r"(a[1]), "r"(a[2]), "r"(a[3]), "r"(b[0]), "r"(b[1]));
}

__device__ __forceinline__ void cp16(uint32_t dst, const void* src) {
    asm volatile("cp.async.cg.shared.global [%0], [%1], 16;\n"
                 :: "r"(dst), "l"(src));
}
__device__ __forceinline__ void cp16z(uint32_t dst, const void* src, int ok) {
    asm volatile("cp.async.cg.shared.global [%0], [%1], 16, %2;\n"
                 :: "r"(dst), "l"(src), "r"(ok ? 16 : 0));
}
__device__ __forceinline__ void cp_commit() {
    asm volatile("cp.async.commit_group;\n" ::: "memory");
}
template <int N>
__device__ __forceinline__ void cp_wait() {
    asm volatile("cp.async.wait_group %0;\n" :: "n"(N) : "memory");
}

// Smem tiles: 128x32 (A / full-width B) and 64x32 (half-width B), stride 36.
#define TSTR 36
#define TILEW (128 * TSTR)                    // uint32 per 128-row tile
#define TILEB (64 * TSTR)                     // uint32 per 64-row tile
#define GEMM_SMEM  (4 * TILEW * 4)            // S=2 x (A + B128)      = 73728 B
#define PROJ_SMEM  (6 * TILEW * 4)            // S=3 x (A + B128)      = 110592 B
#define W13_SMEM   ((2 * TILEW + 4 * TILEB) * 4)  // S=2 x (A + 2xB64) = 73728 B

// ---------------- RMSNorm ---------------------------------------------------
__global__ __launch_bounds__(256) void rmsnorm_kernel(
    const float* __restrict__ x, const float* __restrict__ w,
    float* __restrict__ out)
{
    int t = blockIdx.x;
    const float4* xr = (const float4*)(x + (size_t)t * DD);
    float4 v = xr[threadIdx.x];
    float ss = v.x * v.x + v.y * v.y + v.z * v.z + v.w * v.w;
    #pragma unroll
    for (int o = 16; o; o >>= 1) ss += __shfl_xor_sync(0xffffffffu, ss, o);
    __shared__ float sh[8];
    __shared__ float stot;
    int warp = threadIdx.x >> 5;
    if ((threadIdx.x & 31) == 0) sh[warp] = ss;
    __syncthreads();
    if (threadIdx.x == 0) {
        float s = 0.f;
        #pragma unroll
        for (int i = 0; i < 8; i++) s += sh[i];
        stot = rsqrtf(s / (float)DD + RMS_EPS);
    }
    __syncthreads();
    float sc = stot;
    float4 wv = ((const float4*)w)[threadIdx.x];
    float4 o;
    o.x = v.x * sc * wv.x; o.y = v.y * sc * wv.y;
    o.z = v.z * sc * wv.z; o.w = v.w * sc * wv.w;
    ((float4*)(out + (size_t)t * DD))[threadIdx.x] = o;
}

// ---- 3-stage issue macro for dense proj (A + B 128-row tiles) --------------
#define ISSUE_PROJ(tile, st) do {                                              \
    const int koff_ = (tile) * 32;                                             \
    const uint32_t ao_ = (uint32_t)(st) * TILEW * 4;                           \
    _Pragma("unroll")                                                          \
    for (int i_ = 0; i_ < 4; i_++) {                                           \
        cp16(dA0 + ao_ + i_ * 32 * TSTR * 4, Ap + (size_t)i_ * 32 * Kk + koff_); \
        cp16(dB0 + ao_ + i_ * 32 * TSTR * 4, Wp + (size_t)i_ * 32 * Kk + koff_); \
    }                                                                          \
    cp_commit();                                                               \
} while (0)

// Shared compute step for 128x128 tile (acc[4][4][4])
#define COMPUTE_TILE(Ab, Bb)                                                   \
    _Pragma("unroll")                                                          \
    for (int k8 = 0; k8 < 4; k8++) {                                           \
        int kb = k8 * 8;                                                       \
        uint32_t bf[4][2];                                                     \
        _Pragma("unroll")                                                      \
        for (int ni = 0; ni < 4; ni++) {                                       \
            int n = warpN * 32 + ni * 8 + g;                                   \
            bf[ni][0] = (Bb)[n * TSTR + kb + t];                               \
            bf[ni][1] = (Bb)[n * TSTR + kb + t + 4];                           \
        }                                                                      \
        _Pragma("unroll")                                                      \
        for (int mi = 0; mi < 4; mi++) {                                       \
            int m = warpM * 64 + mi * 16 + g;                                  \
            uint32_t af[4];                                                    \
            af[0] = (Ab)[m * TSTR + kb + t];                                   \
            af[1] = (Ab)[(m + 8) * TSTR + kb + t];                             \
            af[2] = (Ab)[m * TSTR + kb + t + 4];                               \
            af[3] = (Ab)[(m + 8) * TSTR + kb + t + 4];                         \
            _Pragma("unroll")                                                  \
            for (int ni = 0; ni < 4; ni++)                                     \
                mma_tf32(acc[mi][ni], af, bf[ni]);                             \
        }                                                                      \
    }

// ---------------- dense proj GEMM, 3-stage pipeline, 1 barrier/tile ---------
__global__ __launch_bounds__(256) void gemm_mma_proj3(
    const float* __restrict__ A, const float* __restrict__ W,
    const float* __restrict__ resid, float* __restrict__ C,
    int Kk, int Nn)
{
    extern __shared__ uint32_t smbuf[];
    uint32_t* As = smbuf;                  // [3][TILEW]
    uint32_t* Bs = smbuf + 3 * TILEW;      // [3][TILEW]
    const uint32_t smA = (uint32_t)__cvta_generic_to_shared(As);
    const uint32_t smB = (uint32_t)__cvta_generic_to_shared(Bs);

    const int tid = threadIdx.x;
    const int lane = tid & 31, warp = tid >> 5;
    const int warpM = warp >> 2, warpN = warp & 3;
    const int g = lane >> 2, t = lane & 3;
    const int m0 = blockIdx.y * 128, n0 = blockIdx.x * 128;
    float acc[4][4][4] = {};

    const int lrow = tid >> 3;
    const int lkf = (tid & 7) * 4;
    const float* Ap = A + (size_t)(m0 + lrow) * Kk + lkf;
    const float* Wp = W + (size_t)(n0 + lrow) * Kk + lkf;
    const uint32_t dA0 = smA + (lrow * TSTR + lkf) * 4;
    const uint32_t dB0 = smB + (lrow * TSTR + lkf) * 4;

    const int nt = Kk >> 5;
    ISSUE_PROJ(0, 0);
    ISSUE_PROJ(1, 1);

    for (int kt = 0; kt < nt; kt++) {
        if (kt + 1 < nt) cp_wait<1>(); else cp_wait<0>();
        __syncthreads();
        if (kt + 2 < nt) {
            ISSUE_PROJ(kt + 2, (kt + 2) % 3);
        }
        const uint32_t* Ab = As + (kt % 3) * TILEW;
        const uint32_t* Bb = Bs + (kt % 3) * TILEW;
        COMPUTE_TILE(Ab, Bb);
    }

    #pragma unroll
    for (int mi = 0; mi < 4; mi++) {
        int r0 = m0 + warpM * 64 + mi * 16 + g;
        #pragma unroll
        for (int ni = 0; ni < 4; ni++) {
            int c = n0 + warpN * 32 + ni * 8 + 2 * t;
            size_t i0 = (size_t)r0 * Nn + c;
            size_t i1 = i0 + (size_t)8 * Nn;
            float2 v0 = make_float2(acc[mi][ni][0], acc[mi][ni][1]);
            float2 v1 = make_float2(acc[mi][ni][2], acc[mi][ni][3]);
            if (resid) {
                float2 r = *(const float2*)(resid + i0); v0.x += r.x; v0.y += r.y;
                r = *(const float2*)(resid + i1); v1.x += r.x; v1.y += r.y;
            }
            *(float2*)(C + i0) = v0;
            *(float2*)(C + i1) = v1;
        }
    }
}

// ---------------- fused QKV projection --------------------------------------
__global__ __launch_bounds__(256) void gemm_mma_qkv(
    const float* __restrict__ A,
    const float* __restrict__ wq, const float* __restrict__ wk,
    const float* __restrict__ wv,
    float* __restrict__ qo, float* __restrict__ ko, float* __restrict__ vo)
{
    extern __shared__ uint32_t smbuf[];
    uint32_t* As = smbuf;
    uint32_t* Bs = smbuf + 3 * TILEW;
    const uint32_t smA = (uint32_t)__cvta_generic_to_shared(As);
    const uint32_t smB = (uint32_t)__cvta_generic_to_shared(Bs);

    const int tid = threadIdx.x;
    const int lane = tid & 31, warp = tid >> 5;
    const int warpM = warp >> 2, warpN = warp & 3;
    const int g = lane >> 2, t = lane & 3;
    const int m0 = blockIdx.y * 128;
    const int n0t = blockIdx.x * 128;

    const float* W; float* C; int n0;
    if (n0t < DD)            { W = wq; C = qo; n0 = n0t; }
    else if (n0t < 2 * DD)   { W = wk; C = ko; n0 = n0t - DD; }
    else                     { W = wv; C = vo; n0 = n0t - 2 * DD; }

    const int Kk = DD;
    float acc[4][4][4] = {};

    const int lrow = tid >> 3;
    const int lkf = (tid & 7) * 4;
    const float* Ap = A + (size_t)(m0 + lrow) * Kk + lkf;
    const float* Wp = W + (size_t)(n0 + lrow) * Kk + lkf;
    const uint32_t dA0 = smA + (lrow * TSTR + lkf) * 4;
    const uint32_t dB0 = smB + (lrow * TSTR + lkf) * 4;

    const int nt = Kk >> 5;
    ISSUE_PROJ(0, 0);
    ISSUE_PROJ(1, 1);

    for (int kt = 0; kt < nt; kt++) {
        if (kt + 1 < nt) cp_wait<1>(); else cp_wait<0>();
        __syncthreads();
        if (kt + 2 < nt) {
            ISSUE_PROJ(kt + 2, (kt + 2) % 3);
        }
        const uint32_t* Ab = As + (kt % 3) * TILEW;
        const uint32_t* Bb = Bs + (kt % 3) * TILEW;
        COMPUTE_TILE(Ab, Bb);
    }

    #pragma unroll
    for (int mi = 0; mi < 4; mi++) {
        int r0 = m0 + warpM * 64 + mi * 16 + g;
        #pragma unroll
        for (int ni = 0; ni < 4; ni++) {
            int c = n0 + warpN * 32 + ni * 8 + 2 * t;
            size_t i0 = (size_t)r0 * DD + c;
            size_t i1 = i0 + (size_t)8 * DD;
            *(float2*)(C + i0) = make_float2(acc[mi][ni][0], acc[mi][ni][1]);
            *(float2*)(C + i1) = make_float2(acc[mi][ni][2], acc[mi][ni][3]);
        }
    }
}

// ---------------- fused w1+w3 expert GEMM -----------------------------------
__global__ __launch_bounds__(256) void gemm_mma_w13(
    const float* __restrict__ A,
    const float* __restrict__ W1base, const float* __restrict__ W3base)
{
    const int e = blockIdx.z;
    const int count = g_expcnt[e];
    const int m0 = blockIdx.y * 128;
    if (m0 >= count) return;

    extern __shared__ uint32_t smbuf[];
    uint32_t* As  = smbuf;
    uint32_t* B1s = smbuf + 2 * TILEW;
    uint32_t* B3s = smbuf + 2 * TILEW + 2 * TILEB;
    __shared__ int srow[128];
    const uint32_t smA  = (uint32_t)__cvta_generic_to_shared(As);
    const uint32_t smB1 = (uint32_t)__cvta_generic_to_shared(B1s);
    const uint32_t smB3 = (uint32_t)__cvta_generic_to_shared(B3s);

    const int tid = threadIdx.x;
    if (tid < 128) {
        int r = m0 + tid;
        srow[tid] = (r < count) ? g_expslots[e * NTOK + r] : -1;
    }
    __syncthreads();

    const int lane = tid & 31, warp = tid >> 5;
    const int warpM = warp >> 2, warpN = warp & 3;
    const int g = lane >> 2, t = lane & 3;
    const int n0 = blockIdx.x * 64;
    const float* W1 = W1base + (size_t)e * FF * DD;
    const float* W3 = W3base + (size_t)e * FF * DD;
    float acc1[4][2][4] = {};
    float acc3[4][2][4] = {};

    const int lrow = tid >> 3;
    const int lkf = (tid & 7) * 4;

    const float* arp[4];
    int aok[4];
    #pragma unroll
    for (int i = 0; i < 4; i++) {
        int s = srow[lrow + i * 32];
        aok[i] = (s >= 0);
        int arow = (s >= 0) ? (s >> 1) : 0;
        arp[i] = A + (size_t)arow * DD + lkf;
    }
    const float* Wp1 = W1 + (size_t)(n0 + lrow) * DD + lkf;
    const float* Wp3 = W3 + (size_t)(n0 + lrow) * DD + lkf;
    const uint32_t dA0  = smA  + (lrow * TSTR + lkf) * 4;
    const uint32_t dB10 = smB1 + (lrow * TSTR + lkf) * 4;
    const uint32_t dB30 = smB3 + (lrow * TSTR + lkf) * 4;

    const int nt = DD >> 5;
    #pragma unroll
    for (int i = 0; i < 4; i++)
        cp16z(dA0 + i * 32 * TSTR * 4, arp[i], aok[i]);
    #pragma unroll
    for (int i = 0; i < 2; i++) {
        cp16(dB10 + i * 32 * TSTR * 4, Wp1 + (size_t)i * 32 * DD);
        cp16(dB30 + i * 32 * TSTR * 4, Wp3 + (size_t)i * 32 * DD);
    }
    cp_commit();

    for (int kt = 0; kt < nt; kt++) {
        const int buf = kt & 1;
        if (kt + 1 < nt) {
            const int koff = (kt + 1) * 32;
            const uint32_t aoW = (uint32_t)(buf ^ 1) * TILEW * 4;
            const uint32_t aoB = (uint32_t)(buf ^ 1) * TILEB * 4;
            #pragma unroll
            for (int i = 0; i < 4; i++)
                cp16z(dA0 + aoW + i * 32 * TSTR * 4, arp[i] + koff, aok[i]);
            #pragma unroll
            for (int i = 0; i < 2; i++) {
                cp16(dB10 + aoB + i * 32 * TSTR * 4, Wp1 + (size_t)i * 32 * DD + koff);
                cp16(dB30 + aoB + i * 32 * TSTR * 4, Wp3 + (size_t)i * 32 * DD + koff);
            }
            cp_commit();
            cp_wait<1>();
        } else {
            cp_wait<0>();
        }
        __syncthreads();

        const uint32_t* Ab  = As  + buf * TILEW;
        const uint32_t* B1b = B1s + buf * TILEB;
        const uint32_t* B3b = B3s + buf * TILEB;
        #pragma unroll
        for (int k8 = 0; k8 < 4; k8++) {
            int kb = k8 * 8;
            uint32_t bf1[2][2], bf3[2][2];
            #pragma unroll
            for (int ni = 0; ni < 2; ni++) {
                int n = warpN * 16 + ni * 8 + g;
                bf1[ni][0] = B1b[n * TSTR + kb + t];
                bf1[ni][1] = B1b[n * TSTR + kb + t + 4];
                bf3[ni][0] = B3b[n * TSTR + kb + t];
                bf3[ni][1] = B3b[n * TSTR + kb + t + 4];
            }
            #pragma unroll
            for (int mi = 0; mi < 4; mi++) {
                int m = warpM * 64 + mi * 16 + g;
                uint32_t af[4];
                af[0] = Ab[m * TSTR + kb + t];
                af[1] = Ab[(m + 8) * TSTR + kb + t];
                af[2] = Ab[m * TSTR + kb + t + 4];
                af[3] = Ab[(m + 8) * TSTR + kb + t + 4];
                #pragma unroll
                for (int ni = 0; ni < 2; ni++) {
                    mma_tf32(acc1[mi][ni], af, bf1[ni]);
                    mma_tf32(acc3[mi][ni], af, bf3[ni]);
                }
            }
        }
        __syncthreads();
    }

    #pragma unroll
    for (int mi = 0; mi < 4; mi++) {
        int mloc0 = warpM * 64 + mi * 16 + g;
        #pragma unroll
        for (int half = 0; half < 2; half++) {
            int mloc = mloc0 + half * 8;
            int s = srow[mloc];
            if (s < 0) continue;
            #pragma unroll
            for (int ni = 0; ni < 2; ni++) {
                int c = n0 + warpN * 16 + ni * 8 + 2 * t;
                float h1x = acc1[mi][ni][half * 2],     h1y = acc1[mi][ni][half * 2 + 1];
                float h3x = acc3[mi][ni][half * 2],     h3y = acc3[mi][ni][half * 2 + 1];
                float2 o;
                o.x = (h1x / (1.f + expf(-h1x))) * h3x;
                o.y = (h1y / (1.f + expf(-h1y))) * h3y;
                *(float2*)(&g_hidden[(size_t)s * FF + c]) = o;
            }
        }
    }
}

// ---------------- w2 expert GEMM --------------------------------------------
__global__ __launch_bounds__(256) void gemm_mma_w2(
    const float* __restrict__ A, const float* __restrict__ Wbase)
{
    const int e = blockIdx.z;
    const int count = g_expcnt[e];
    const int m0 = blockIdx.y * 128;
    if (m0 >= count) return;

    extern __shared__ uint32_t smbuf[];
    uint32_t* As = smbuf;
    uint32_t* Bs = smbuf + 2 * TILEW;
    __shared__ int srow[128];
    const uint32_t smA = (uint32_t)__cvta_generic_to_shared(As);
    const uint32_t smB = (uint32_t)__cvta_generic_to_shared(Bs);

    const int tid = threadIdx.x;
    if (tid < 128) {
        int r = m0 + tid;
        srow[tid] = (r < count) ? g_expslots[e * NTOK + r] : -1;
    }
    __syncthreads();

    const int lane = tid & 31, warp = tid >> 5;
    const int warpM = warp >> 2, warpN = warp & 3;
    const int g = lane >> 2, t = lane & 3;
    const int n0 = blockIdx.x * 128;
    const float* W = Wbase + (size_t)e * DD * FF;
    const int Kk = FF;
    float acc[4][4][4] = {};

    const int lrow = tid >> 3;
    const int lkf = (tid & 7) * 4;

    const float* arp[4];
    int aok[4];
    #pragma unroll
    for (int i = 0; i < 4; i++) {
        int s = srow[lrow + i * 32];
        aok[i] = (s >= 0);
        int arow = (s >= 0) ? s : 0;
        arp[i] = A + (size_t)arow * FF + lkf;
    }
    const float* Wp = W + (size_t)(n0 + lrow) * Kk + lkf;
    const uint32_t dA0 = smA + (lrow * TSTR + lkf) * 4;
    const uint32_t dB0 = smB + (lrow * TSTR + lkf) * 4;

    const int nt = Kk >> 5;
    #pragma unroll
    for (int i = 0; i < 4; i++) {
        cp16z(dA0 + i * 32 * TSTR * 4, arp[i], aok[i]);
        cp16(dB0 + i * 32 * TSTR * 4, Wp + (size_t)i * 32 * Kk);
    }
    cp_commit();

    for (int kt = 0; kt < nt; kt++) {
        const int buf = kt & 1;
        if (kt + 1 < nt) {
            const int koff = (kt + 1) * 32;
            const uint32_t bo = (uint32_t)(buf ^ 1) * TILEW * 4;
            #pragma unroll
            for (int i = 0; i < 4; i++) {
                cp16z(dA0 + bo + i * 32 * TSTR * 4, arp[i] + koff, aok[i]);
                cp16(dB0 + bo + i * 32 * TSTR * 4, Wp + (size_t)i * 32 * Kk + koff);
            }
            cp_commit();
            cp_wait<1>();
        } else {
            cp_wait<0>();
        }
        __syncthreads();

        const uint32_t* Ab = As + buf * TILEW;
        const uint32_t* Bb = Bs + buf * TILEW;
        COMPUTE_TILE(Ab, Bb);
        __syncthreads();
    }

    #pragma unroll
    for (int mi = 0; mi < 4; mi++) {
        int mloc0 = warpM * 64 + mi * 16 + g;
        #pragma unroll
        for (int half = 0; half < 2; half++) {
            int mloc = mloc0 + half * 8;
            int s = srow[mloc];
            if (s < 0) continue;
            #pragma unroll
            for (int ni = 0; ni < 4; ni++) {
                int c = n0 + warpN * 32 + ni * 8 + 2 * t;
                *(float2*)(&g_ypair[(size_t)s * DD + c]) =
                    make_float2(acc[mi][ni][half * 2], acc[mi][ni][half * 2 + 1]);
            }
        }
    }
}

// ---------------- RoPE (q and k in place) -----------------------------------
__global__ void rope_kernel(float* __restrict__ qh, float* __restrict__ kh,
                            const float* __restrict__ cosb,
                            const float* __restrict__ sinb)
{
    int idx = blockIdx.x * blockDim.x + threadIdx.x;
    int i = idx & 31;
    int th = idx >> 5;
    int t = th >> 4;
    int s = t & (SS - 1);
    float c = cosb[s * 32 + i], sn = sinb[s * 32 + i];
    size_t base = (size_t)th * HDD + i * 2;
    float xr = qh[base], xi = qh[base + 1];
    qh[base]     = xr * c - xi * sn;
    qh[base + 1] = xr * sn + xi * c;
    xr = kh[base]; xi = kh[base + 1];
    kh[base]     = xr * c - xi * sn;
    kh[base + 1] = xr * sn + xi * c;
}

// ---------------- Flash attention (tf32 tensor cores) -----------------------
// CTA: 64 q-rows x one (b,h); 4 warps, warp = 16 q-rows, full N=64 per warp.
// smem: Qs/Ks/Vt/Ps each 64 rows x stride 68 floats.
#define ASTR 68
#define ATT_SMEM (4 * 64 * ASTR * 4)
__global__ __launch_bounds__(128) void attn_mma_kernel(
    const float* __restrict__ Q, const float* __restrict__ K,
    const float* __restrict__ V, float* __restrict__ O,
    const int* __restrict__ causal_flag)
{
    extern __shared__ float sm[];
    float* Qs = sm;
    float* Ks = Qs + 64 * ASTR;
    float* Vt = Ks + 64 * ASTR;   // transposed: Vt[d][kpos]
    float* Ps = Vt + 64 * ASTR;
    const int qt = blockIdx.x, bh = blockIdx.y;
    const int b = bh >> 4, h = bh & 15;
    const int tid = threadIdx.x;
    const int warp = tid >> 5, lane = tid & 31;
    const int g = lane >> 2, t = lane & 3;
    const int causal = *causal_flag;
    const size_t base = (size_t)b * SS * DD + (size_t)h * HDD;
    const float* Qb = Q + base;
    const float* Kb = K + base;
    const float* Vb = V + base;
    const int q0 = qt * 64;

    // load Q tile, pre-scaled by 1/sqrt(HD) (exact: power of 2)
    {
        int row = tid >> 1;
        int cb = (tid & 1) * 32;
        const float* src = Qb + (size_t)(q0 + row) * DD + cb;
        #pragma unroll
        for (int j = 0; j < 8; j++) {
            float4 v = *(const float4*)(src + j * 4);
            float* d = &Qs[row * ASTR + cb + j * 4];
            d[0] = v.x * ATT_SCALE; d[1] = v.y * ATT_SCALE;
            d[2] = v.z * ATT_SCALE; d[3] = v.w * ATT_SCALE;
        }
    }

    float m_run0 = -1e30f, m_run1 = -1e30f;
    float l_run0 = 0.f, l_run1 = 0.f;
    float Oacc[8][4] = {};
    const int mrow = warp * 16 + g;

    const int ktmax = causal ? qt : (SS / 64 - 1);
    for (int kt = 0; kt <= ktmax; kt++) {
        __syncthreads();   // prev tile fully consumed
        {
            int row = tid >> 1;
            int cb = (tid & 1) * 32;
            const float* ksrc = Kb + (size_t)(kt * 64 + row) * DD + cb;
            const float* vsrc = Vb + (size_t)(kt * 64 + row) * DD + cb;
            #pragma unroll
            for (int j = 0; j < 8; j++) {
                float4 kv = *(const float4*)(ksrc + j * 4);
                float* d = &Ks[row * ASTR + cb + j * 4];
                d[0] = kv.x; d[1] = kv.y; d[2] = kv.z; d[3] = kv.w;
                float4 vv = *(const float4*)(vsrc + j * 4);
                int c = cb + j * 4;
                Vt[(c + 0) * ASTR + row] = vv.x;
                Vt[(c + 1) * ASTR + row] = vv.y;
                Vt[(c + 2) * ASTR + row] = vv.z;
                Vt[(c + 3) * ASTR + row] = vv.w;
            }
        }
        __syncthreads();

        // S = (Q*scale) @ K^T   (warp rows mrow, mrow+8; cols 0..63)
        float sacc[8][4] = {};
        const uint32_t* Qsu = (const uint32_t*)Qs;
        const uint32_t* Ksu = (const uint32_t*)Ks;
        #pragma unroll
        for (int k8 = 0; k8 < 8; k8++) {
            int kb = k8 * 8;
            uint32_t af[4];
            af[0] = Qsu[mrow * ASTR + kb + t];
            af[1] = Qsu[(mrow + 8) * ASTR + kb + t];
            af[2] = Qsu[mrow * ASTR + kb + t + 4];
            af[3] = Qsu[(mrow + 8) * ASTR + kb + t + 4];
            #pragma unroll
            for (int ni = 0; ni < 8; ni++) {
                uint32_t bf[2];
                bf[0] = Ksu[(ni * 8 + g) * ASTR + kb + t];
                bf[1] = Ksu[(ni * 8 + g) * ASTR + kb + t + 4];
                mma_tf32(sacc[ni], af, bf);
            }
        }

        const int row0 = q0 + mrow, row1 = row0 + 8;
        if (causal && kt == qt) {
            #pragma unroll
            for (int ni = 0; ni < 8; ni++) {
                int c0 = kt * 64 + ni * 8 + 2 * t;
                if (c0     > row0) sacc[ni][0] = -1e30f;
                if (c0 + 1 > row0) sacc[ni][1] = -1e30f;
                if (c0     > row1) sacc[ni][2] = -1e30f;
                if (c0 + 1 > row1) sacc[ni][3] = -1e30f;
            }
        }

        // online softmax (rows g / g+8 are quad-local: shfl over t only)
        float ml0 = -1e30f, ml1 = -1e30f;
        #pragma unroll
        for (int ni = 0; ni < 8; ni++) {
            ml0 = fmaxf(ml0, fmaxf(sacc[ni][0], sacc[ni][1]));
            ml1 = fmaxf(ml1, fmaxf(sacc[ni][2], sacc[ni][3]));
        }
        ml0 = fmaxf(ml0, __shfl_xor_sync(0xffffffffu, ml0, 1));
        ml0 = fmaxf(ml0, __shfl_xor_sync(0xffffffffu, ml0, 2));
        ml1 = fmaxf(ml1, __shfl_xor_sync(0xffffffffu, ml1, 1));
        ml1 = fmaxf(ml1, __shfl_xor_sync(0xffffffffu, ml1, 2));
        float mn0 = fmaxf(m_run0, ml0), mn1 = fmaxf(m_run1, ml1);
        float a0 = expf(m_run0 - mn0), a1 = expf(m_run1 - mn1);
        float ps0 = 0.f, ps1 = 0.f;
        #pragma unroll
        for (int ni = 0; ni < 8; ni++) {
            float p0 = expf(sacc[ni][0] - mn0);
            float p1 = expf(sacc[ni][1] - mn0);
            float p2 = expf(sacc[ni][2] - mn1);
            float p3 = expf(sacc[ni][3] - mn1);
            ps0 += p0 + p1; ps1 += p2 + p3;
            int cl = ni * 8 + 2 * t;
            *(float2*)&Ps[mrow * ASTR + cl]       = make_float2(p0, p1);
            *(float2*)&Ps[(mrow + 8) * ASTR + cl] = make_float2(p2, p3);
        }
        ps0 += __shfl_xor_sync(0xffffffffu, ps0, 1);
        ps0 += __shfl_xor_sync(0xffffffffu, ps0, 2);
        ps1 += __shfl_xor_sync(0xffffffffu, ps1, 1);
        ps1 += __shfl_xor_sync(0xffffffffu, ps1, 2);
        l_run0 = l_run0 * a0 + ps0;
        l_run1 = l_run1 * a1 + ps1;
        m_run0 = mn0; m_run1 = mn1;
        #pragma unroll
        for (int ni = 0; ni < 8; ni++) {
            Oacc[ni][0] *= a0; Oacc[ni][1] *= a0;
            Oacc[ni][2] *= a1; Oacc[ni][3] *= a1;
        }
        __syncwarp();   // Ps rows are warp-private; make writes visible

        // O += P @ V   (A = Ps rows, B = Vt[d][kpos])
        const uint32_t* Psu = (const uint32_t*)Ps;
        const uint32_t* Vtu = (const uint32_t*)Vt;
        #pragma unroll
        for (int k8 = 0; k8 < 8; k8++) {
            int kb = k8 * 8;
            uint32_t af[4];
            af[0] = Psu[mrow * ASTR + kb + t];
            af[1] = Psu[(mrow + 8) * ASTR + kb + t];
            af[2] = Psu[mrow * ASTR + kb + t + 4];
            af[3] = Psu[(mrow + 8) * ASTR + kb + t + 4];
            #pragma unroll
            for (int ni = 0; ni < 8; ni++) {
                uint32_t bf[2];
                bf[0] = Vtu[(ni * 8 + g) * ASTR + kb + t];
                bf[1] = Vtu[(ni * 8 + g) * ASTR + kb + t + 4];
                mma_tf32(Oacc[ni], af, bf);
            }
        }
    }

    float i0 = 1.f / l_run0, i1 = 1.f / l_run1;
    const int row0 = q0 + mrow;
    float* dst0 = O + (size_t)(b * SS + row0) * DD + (size_t)h * HDD;
    float* dst1 = dst0 + (size_t)8 * DD;
    #pragma unroll
    for (int ni = 0; ni < 8; ni++) {
        int d = ni * 8 + 2 * t;
        *(float2*)(dst0 + d) = make_float2(Oacc[ni][0] * i0, Oacc[ni][1] * i0);
        *(float2*)(dst1 + d) = make_float2(Oacc[ni][2] * i1, Oacc[ni][3] * i1);
    }
}

// ---------------- router + top-2 --------------------------------------------
__global__ void zero_counts_kernel()
{
    if (threadIdx.x < EE) g_expcnt[threadIdx.x] = 0;
}

__global__ __launch_bounds__(256) void router_kernel(
    const float* __restrict__ xn, const float* __restrict__ rw,
    const float* __restrict__ rb)
{
    int t = blockIdx.x;
    float4 xv = ((const float4*)(xn + (size_t)t * DD))[threadIdx.x];
    float lg[EE];
    #pragma unroll
    for (int e = 0; e < EE; e++) {
        float4 wv = ((const float4*)(rw + (size_t)e * DD))[threadIdx.x];
        lg[e] = xv.x * wv.x + xv.y * wv.y + xv.z * wv.z + xv.w * wv.w;
    }
    #pragma unroll
    for (int o = 16; o; o >>= 1)
        #pragma unroll
        for (int e = 0; e < EE; e++)
            lg[e] += __shfl_xor_sync(0xffffffffu, lg[e], o);
    __shared__ float sh[EE][8];
    int warp = threadIdx.x >> 5;
    if ((threadIdx.x & 31) == 0)
        #pragma unroll
        for (int e = 0; e < EE; e++) sh[e][warp] = lg[e];
    __syncthreads();
    if (threadIdx.x == 0) {
        float logits[EE];
        #pragma unroll
        for (int e = 0; e < EE; e++) {
            float s = rb[e];
            #pragma unroll
            for (int w = 0; w < 8; w++) s += sh[e][w];
            logits[e] = s;
        }
        int i0 = 0;
        #pragma unroll
        for (int e = 1; e < EE; e++) if (logits[e] > logits[i0]) i0 = e;
        int i1 = -1;
        #pragma unroll
        for (int e = 0; e < EE; e++)
            if (e != i0 && (i1 < 0 || logits[e] > logits[i1])) i1 = e;
        float ex = expf(logits[i1] - logits[i0]);
        float denom = 1.f + ex;
        float p0 = 1.f / denom, p1 = ex / denom;
        int s0 = atomicAdd(&g_expcnt[i0], 1);
        g_expslots[i0 * NTOK + s0] = 2 * t;
        g_gate[2 * t] = p0;
        int s1 = atomicAdd(&g_expcnt[i1], 1);
        g_expslots[i1 * NTOK + s1] = 2 * t + 1;
        g_gate[2 * t + 1] = p1;
    }
}

// ---------------- final combine ---------------------------------------------
__global__ __launch_bounds__(256) void combine_kernel(float* __restrict__ out)
{
    int idx = blockIdx.x * 256 + threadIdx.x;
    int t = idx >> 8;
    int col = idx & 255;
    float g0 = g_gate[2 * t], g1 = g_gate[2 * t + 1];
    float4 hv = ((const float4*)g_h)[idx];
    float4 y0 = ((const float4*)g_ypair)[(size_t)(2 * t) * 256 + col];
    float4 y1 = ((const float4*)g_ypair)[(size_t)(2 * t + 1) * 256 + col];
    float4 o;
    o.x = hv.x + g0 * y0.x + g1 * y1.x;
    o.y = hv.y + g0 * y0.y + g1 * y1.y;
    o.z = hv.z + g0 * y0.z + g1 * y1.z;
    o.w = hv.w + g0 * y0.w + g1 * y1.w;
    ((float4*)out)[idx] = o;
}

// ---------------- launch ----------------------------------------------------
extern "C" void kernel_launch(void* const* d_in, const int* in_sizes, int n_in,
                              void* d_out, int out_size)
{
    const float* q     = (const float*)d_in[0];
    const float* fcos  = (const float*)d_in[3];
    const float* fsin  = (const float*)d_in[4];
    const float* att_w = (const float*)d_in[5];
    const float* ffn_w = (const float*)d_in[6];
    const float* wq    = (const float*)d_in[7];
    const float* wk    = (const float*)d_in[8];
    const float* wv    = (const float*)d_in[9];
    const float* wo    = (const float*)d_in[10];
    const float* rw    = (const float*)d_in[11];
    const float* rb    = (const float*)d_in[12];
    const float* w1    = (const float*)d_in[13];
    const float* w2    = (const float*)d_in[14];
    const float* w3    = (const float*)d_in[15];
    const int*   causal= (const int*)d_in[16];
    float* out = (float*)d_out;

    float *p_xn, *p_qh, *p_kh, *p_vh, *p_att, *p_h, *p_hidden;
    cudaGetSymbolAddress((void**)&p_xn, g_xn);
    cudaGetSymbolAddress((void**)&p_qh, g_qh);
    cudaGetSymbolAddress((void**)&p_kh, g_kh);
    cudaGetSymbolAddress((void**)&p_vh, g_vh);
    cudaGetSymbolAddress((void**)&p_att, g_att);
    cudaGetSymbolAddress((void**)&p_h, g_h);
    cudaGetSymbolAddress((void**)&p_hidden, g_hidden);

    cudaFuncSetAttribute(attn_mma_kernel,
                         cudaFuncAttributeMaxDynamicSharedMemorySize, ATT_SMEM);
    cudaFuncSetAttribute(gemm_mma_proj3,
                         cudaFuncAttributeMaxDynamicSharedMemorySize, PROJ_SMEM);
    cudaFuncSetAttribute(gemm_mma_qkv,
                         cudaFuncAttributeMaxDynamicSharedMemorySize, PROJ_SMEM);
    cudaFuncSetAttribute(gemm_mma_w13,
                         cudaFuncAttributeMaxDynamicSharedMemorySize, W13_SMEM);
    cudaFuncSetAttribute(gemm_mma_w2,
                         cudaFuncAttributeMaxDynamicSharedMemorySize, GEMM_SMEM);

    // 1. qn = rmsnorm(q) * att_norm_w
    rmsnorm_kernel<<<NTOK, 256>>>(q, att_w, p_xn);

    // 2. fused QKV projection
    gemm_mma_qkv<<<dim3(3 * DD / 128, NTOK / 128), 256, PROJ_SMEM>>>(
        p_xn, wq, wk, wv, p_qh, p_kh, p_vh);

    // 3. RoPE
    rope_kernel<<<(NTOK * HH * (HDD / 2)) / 256, 256>>>(p_qh, p_kh, fcos, fsin);

    // 4. flash attention (tf32 tensor cores)
    attn_mma_kernel<<<dim3(SS / 64, BB * HH), 128, ATT_SMEM>>>(
        p_qh, p_kh, p_vh, p_att, causal);

    // 5. h = q + att @ wo^T
    gemm_mma_proj3<<<dim3(DD / 128, NTOK / 128), 256, PROJ_SMEM>>>(
        p_att, wo, q, p_h, DD, DD);

    // 6. hn = rmsnorm(h)
    rmsnorm_kernel<<<NTOK, 256>>>(p_h, ffn_w, p_xn);

    // 7. routing
    zero_counts_kernel<<<1, 32>>>();
    router_kernel<<<NTOK, 256>>>(p_xn, rw, rb);

    // 8. MoE: fused w1+w3, then w2
    gemm_mma_w13<<<dim3(FF / 64, NTOK / 128, EE), 256, W13_SMEM>>>(p_xn, w1, w3);
    gemm_mma_w2<<<dim3(DD / 128, NTOK / 128, EE), 256, GEMM_SMEM>>>(p_hidden, w2);

    // 9. combine
    combine_kernel<<<NTOK, 256>>>(out);
}